// round 1
// baseline (speedup 1.0000x reference)
#include <cuda_runtime.h>
#include <math.h>

#define C_EMBED 768
#define NH 12
#define HD 64
#define BATCH 2
#define SEQ 4096
#define MROWS (BATCH*SEQ)        // 8192
#define C3 (3*C_EMBED)           // 2304

// Scratch (no allocations allowed)
__device__ float g_qkv[(size_t)MROWS * C3];       // 75.5 MB
__device__ float g_att[(size_t)MROWS * C_EMBED];  // 25 MB

// ---------------------------------------------------------------------------
// GEMM: C[M,N] = A[M,K] @ B[K,N] + bias[N]
// 128x128 tile, BK=16, 256 threads, 8x8 per-thread microtile.
// M,N,K all divisible by tile dims for our shapes (no bounds checks).
// ---------------------------------------------------------------------------
__global__ void __launch_bounds__(256) gemm_bias_kernel(
    const float* __restrict__ A, const float* __restrict__ Bm,
    const float* __restrict__ bias, float* __restrict__ Cm,
    int M, int N, int K)
{
    __shared__ float As[16][132];   // transposed A tile: As[k][m]
    __shared__ float Bs[16][132];   // Bs[k][n]

    const int tid = threadIdx.x;
    const int row0 = blockIdx.y * 128;
    const int col0 = blockIdx.x * 128;
    const int ty = tid >> 4;   // 0..15
    const int tx = tid & 15;   // 0..15

    float acc[8][8];
#pragma unroll
    for (int i = 0; i < 8; i++)
#pragma unroll
        for (int j = 0; j < 8; j++) acc[i][j] = 0.f;

    for (int k0 = 0; k0 < K; k0 += 16) {
        // Load A tile (128x16) -> As transposed. 512 float4 loads, 2/thread.
#pragma unroll
        for (int u = 0; u < 2; u++) {
            int idx = tid * 2 + u;           // 0..511
            int r   = idx >> 2;              // 0..127
            int c4  = idx & 3;               // 0..3
            float4 v = *(const float4*)&A[(size_t)(row0 + r) * K + k0 + c4 * 4];
            As[c4*4+0][r] = v.x;
            As[c4*4+1][r] = v.y;
            As[c4*4+2][r] = v.z;
            As[c4*4+3][r] = v.w;
        }
        // Load B tile (16x128). 512 float4 loads, 2/thread.
#pragma unroll
        for (int u = 0; u < 2; u++) {
            int idx = tid * 2 + u;           // 0..511
            int r   = idx >> 5;              // 0..15
            int c4  = idx & 31;              // 0..31
            float4 v = *(const float4*)&Bm[(size_t)(k0 + r) * N + col0 + c4 * 4];
            *(float4*)&Bs[r][c4 * 4] = v;
        }
        __syncthreads();

#pragma unroll
        for (int kk = 0; kk < 16; kk++) {
            float a[8], b[8];
#pragma unroll
            for (int i = 0; i < 8; i++) a[i] = As[kk][ty * 8 + i];
#pragma unroll
            for (int j = 0; j < 8; j++) b[j] = Bs[kk][tx * 8 + j];
#pragma unroll
            for (int i = 0; i < 8; i++)
#pragma unroll
                for (int j = 0; j < 8; j++)
                    acc[i][j] += a[i] * b[j];
        }
        __syncthreads();
    }

#pragma unroll
    for (int i = 0; i < 8; i++) {
        int r = row0 + ty * 8 + i;
#pragma unroll
        for (int j = 0; j < 8; j += 4) {
            int c = col0 + tx * 8 + j;
            float4 v;
            v.x = acc[i][j+0] + bias[c+0];
            v.y = acc[i][j+1] + bias[c+1];
            v.z = acc[i][j+2] + bias[c+2];
            v.w = acc[i][j+3] + bias[c+3];
            *(float4*)&Cm[(size_t)r * N + c] = v;
        }
    }
}

// ---------------------------------------------------------------------------
// Flash attention (causal), fp32. One CTA = 64 query rows for one (b, h).
// 256 threads as 16x16; each thread owns a 4x4 of S / O.
// Online softmax; P staged through smem for the PV product.
// ---------------------------------------------------------------------------
#define ATTN_SMEM_FLOATS (64*65*3 + 64*68)   // Qt, Kt, Ps (stride 65) + Vs (stride 68)
#define ATTN_SMEM_BYTES  (ATTN_SMEM_FLOATS * 4)   // 67328

__global__ void __launch_bounds__(256) attn_kernel(
    const float* __restrict__ qkv, float* __restrict__ attout)
{
    extern __shared__ float sm[];
    float* Qt = sm;               // Qt[d*65 + row]   (d-major)
    float* Kt = Qt + 64 * 65;     // Kt[d*65 + col]
    float* Ps = Kt + 64 * 65;     // Ps[key*65 + row]
    float* Vs = Ps + 64 * 65;     // Vs[key*68 + dim]

    const int qt  = blockIdx.x;   // query tile (0..63)
    const int h   = blockIdx.y;
    const int b   = blockIdx.z;
    const int tid = threadIdx.x;
    const int ty  = tid >> 4;     // 0..15
    const int tx  = tid & 15;     // 0..15

    const float* qbase = qkv + (size_t)b * SEQ * C3 + h * HD;
    const float* kbase = qbase + C_EMBED;
    const float* vbase = qbase + 2 * C_EMBED;

    // Load Q tile transposed: Qt[d][r] = q[qt*64+r][d]
#pragma unroll
    for (int u = 0; u < 4; u++) {
        int idx = tid + u * 256;      // 0..1023
        int r   = idx >> 4;           // 0..63
        int c4  = idx & 15;           // d = c4*4
        float4 v = *(const float4*)&qbase[(size_t)(qt * 64 + r) * C3 + c4 * 4];
        Qt[(c4*4+0)*65 + r] = v.x;
        Qt[(c4*4+1)*65 + r] = v.y;
        Qt[(c4*4+2)*65 + r] = v.z;
        Qt[(c4*4+3)*65 + r] = v.w;
    }

    float m[4], l[4], o[4][4];
#pragma unroll
    for (int i = 0; i < 4; i++) {
        m[i] = -1e30f; l[i] = 0.f;
#pragma unroll
        for (int j = 0; j < 4; j++) o[i][j] = 0.f;
    }

    const float scale = 0.125f;   // 1/sqrt(64)

    for (int j0 = 0; j0 <= qt; j0++) {
        __syncthreads();   // previous iteration's Ps/Vs reads complete
        // Load K tile transposed + V tile direct
#pragma unroll
        for (int u = 0; u < 4; u++) {
            int idx = tid + u * 256;
            int r   = idx >> 4;
            int c4  = idx & 15;
            float4 v = *(const float4*)&kbase[(size_t)(j0 * 64 + r) * C3 + c4 * 4];
            Kt[(c4*4+0)*65 + r] = v.x;
            Kt[(c4*4+1)*65 + r] = v.y;
            Kt[(c4*4+2)*65 + r] = v.z;
            Kt[(c4*4+3)*65 + r] = v.w;
            float4 w = *(const float4*)&vbase[(size_t)(j0 * 64 + r) * C3 + c4 * 4];
            *(float4*)&Vs[r * 68 + c4 * 4] = w;
        }
        __syncthreads();

        // S = Q @ K^T  (thread: rows ty*4+i, key cols tx*4+j)
        float s[4][4];
#pragma unroll
        for (int i = 0; i < 4; i++)
#pragma unroll
            for (int j = 0; j < 4; j++) s[i][j] = 0.f;

        for (int d = 0; d < 64; d++) {
            float a[4], bb[4];
#pragma unroll
            for (int i = 0; i < 4; i++) a[i]  = Qt[d * 65 + ty * 4 + i];
#pragma unroll
            for (int j = 0; j < 4; j++) bb[j] = Kt[d * 65 + tx * 4 + j];
#pragma unroll
            for (int i = 0; i < 4; i++)
#pragma unroll
                for (int j = 0; j < 4; j++)
                    s[i][j] += a[i] * bb[j];
        }

        // Causal mask + online softmax (row groups of 16 lanes share ty)
#pragma unroll
        for (int i = 0; i < 4; i++) {
            int qrow = qt * 64 + ty * 4 + i;
            float mloc = -1e30f;
#pragma unroll
            for (int j = 0; j < 4; j++) {
                int kcol = j0 * 64 + tx * 4 + j;
                s[i][j] = (kcol <= qrow) ? s[i][j] * scale : -1e30f;
                mloc = fmaxf(mloc, s[i][j]);
            }
#pragma unroll
            for (int off = 8; off > 0; off >>= 1)
                mloc = fmaxf(mloc, __shfl_xor_sync(0xffffffffu, mloc, off));
            float mnew = fmaxf(m[i], mloc);
            float corr = __expf(m[i] - mnew);
            float rsum = 0.f;
#pragma unroll
            for (int j = 0; j < 4; j++) {
                float p = __expf(s[i][j] - mnew);
                s[i][j] = p;
                rsum += p;
            }
#pragma unroll
            for (int off = 8; off > 0; off >>= 1)
                rsum += __shfl_xor_sync(0xffffffffu, rsum, off);
            l[i] = l[i] * corr + rsum;
            m[i] = mnew;
#pragma unroll
            for (int j = 0; j < 4; j++) o[i][j] *= corr;
        }

        // Stage P transposed: Ps[key][qrow]
#pragma unroll
        for (int i = 0; i < 4; i++)
#pragma unroll
            for (int j = 0; j < 4; j++)
                Ps[(tx * 4 + j) * 65 + ty * 4 + i] = s[i][j];
        __syncthreads();

        // O += P @ V  (thread: rows ty*4+i, dim cols tx*4+j)
        for (int k = 0; k < 64; k++) {
            float pa[4], pv[4];
#pragma unroll
            for (int i = 0; i < 4; i++) pa[i] = Ps[k * 65 + ty * 4 + i];
#pragma unroll
            for (int j = 0; j < 4; j++) pv[j] = Vs[k * 68 + tx * 4 + j];
#pragma unroll
            for (int i = 0; i < 4; i++)
#pragma unroll
                for (int j = 0; j < 4; j++)
                    o[i][j] += pa[i] * pv[j];
        }
    }

    // Normalize and write to [b, t, h*64+dim] layout (ready for output proj)
#pragma unroll
    for (int i = 0; i < 4; i++) {
        int t = qt * 64 + ty * 4 + i;
        float inv = 1.f / l[i];
#pragma unroll
        for (int j = 0; j < 4; j++) {
            attout[(size_t)(b * SEQ + t) * C_EMBED + h * HD + tx * 4 + j] = o[i][j] * inv;
        }
    }
}

// ---------------------------------------------------------------------------
extern "C" void kernel_launch(void* const* d_in, const int* in_sizes, int n_in,
                              void* d_out, int out_size)
{
    const float* x     = (const float*)d_in[0];
    const float* Wqkv  = (const float*)d_in[1];
    const float* bqkv  = (const float*)d_in[2];
    const float* Wproj = (const float*)d_in[3];
    const float* bproj = (const float*)d_in[4];
    float* out = (float*)d_out;

    float *qkv, *att;
    cudaGetSymbolAddress((void**)&qkv, g_qkv);
    cudaGetSymbolAddress((void**)&att, g_att);

    cudaFuncSetAttribute(attn_kernel, cudaFuncAttributeMaxDynamicSharedMemorySize,
                         ATTN_SMEM_BYTES);

    // 1) QKV projection: [8192,768] @ [768,2304] + b
    dim3 g1(C3 / 128, MROWS / 128);
    gemm_bias_kernel<<<g1, 256>>>(x, Wqkv, bqkv, qkv, MROWS, C3, C_EMBED);

    // 2) Causal flash attention per (b,h), 64-query tiles
    dim3 g2(SEQ / 64, NH, BATCH);
    attn_kernel<<<g2, 256, ATTN_SMEM_BYTES>>>(qkv, att);

    // 3) Output projection: [8192,768] @ [768,768] + b
    dim3 g3(C_EMBED / 128, MROWS / 128);
    gemm_bias_kernel<<<g3, 256>>>(att, Wproj, bproj, out, MROWS, C_EMBED, C_EMBED);
}

// round 3
// speedup vs baseline: 1.4185x; 1.4185x over previous
#include <cuda_runtime.h>
#include <math.h>
#include <stdint.h>

#define C_EMBED 768
#define NH 12
#define HD 64
#define BATCH 2
#define SEQ 4096
#define MROWS (BATCH*SEQ)        // 8192
#define C3 (3*C_EMBED)           // 2304

// Scratch (no allocations allowed)
__device__ float g_qkv[(size_t)MROWS * C3];       // 75.5 MB
__device__ float g_att[(size_t)MROWS * C_EMBED];  // 25 MB

// ---------------------------------------------------------------------------
// fp32 GEMM with bias (verified R1 kernel, unchanged): C = A@B + bias
// ---------------------------------------------------------------------------
__global__ void __launch_bounds__(256) gemm_bias_kernel(
    const float* __restrict__ A, const float* __restrict__ Bm,
    const float* __restrict__ bias, float* __restrict__ Cm,
    int M, int N, int K)
{
    __shared__ float As[16][132];
    __shared__ float Bs[16][132];

    const int tid = threadIdx.x;
    const int row0 = blockIdx.y * 128;
    const int col0 = blockIdx.x * 128;
    const int ty = tid >> 4;
    const int tx = tid & 15;

    float acc[8][8];
#pragma unroll
    for (int i = 0; i < 8; i++)
#pragma unroll
        for (int j = 0; j < 8; j++) acc[i][j] = 0.f;

    for (int k0 = 0; k0 < K; k0 += 16) {
#pragma unroll
        for (int u = 0; u < 2; u++) {
            int idx = tid * 2 + u;
            int r   = idx >> 2;
            int c4  = idx & 3;
            float4 v = *(const float4*)&A[(size_t)(row0 + r) * K + k0 + c4 * 4];
            As[c4*4+0][r] = v.x;
            As[c4*4+1][r] = v.y;
            As[c4*4+2][r] = v.z;
            As[c4*4+3][r] = v.w;
        }
#pragma unroll
        for (int u = 0; u < 2; u++) {
            int idx = tid * 2 + u;
            int r   = idx >> 5;
            int c4  = idx & 31;
            float4 v = *(const float4*)&Bm[(size_t)(k0 + r) * N + col0 + c4 * 4];
            *(float4*)&Bs[r][c4 * 4] = v;
        }
        __syncthreads();

#pragma unroll
        for (int kk = 0; kk < 16; kk++) {
            float a[8], b[8];
#pragma unroll
            for (int i = 0; i < 8; i++) a[i] = As[kk][ty * 8 + i];
#pragma unroll
            for (int j = 0; j < 8; j++) b[j] = Bs[kk][tx * 8 + j];
#pragma unroll
            for (int i = 0; i < 8; i++)
#pragma unroll
                for (int j = 0; j < 8; j++)
                    acc[i][j] += a[i] * b[j];
        }
        __syncthreads();
    }

#pragma unroll
    for (int i = 0; i < 8; i++) {
        int r = row0 + ty * 8 + i;
#pragma unroll
        for (int j = 0; j < 8; j += 4) {
            int c = col0 + tx * 8 + j;
            float4 v;
            v.x = acc[i][j+0] + bias[c+0];
            v.y = acc[i][j+1] + bias[c+1];
            v.z = acc[i][j+2] + bias[c+2];
            v.w = acc[i][j+3] + bias[c+3];
            *(float4*)&Cm[(size_t)r * N + c] = v;
        }
    }
}

// ===========================================================================
// tf32 mma.sync flash attention (causal)
// CTA: 64 query rows x (h,b). 128 threads = 4 warps; warp owns 16 rows.
// S = Q K^T and O += P V via mma.sync.aligned.m16n8k8.row.col.f32.tf32.tf32.f32
// ===========================================================================

__device__ __forceinline__ uint32_t f2tf32(float v) {
    uint32_t t;
    asm("cvt.rna.tf32.f32 %0, %1;" : "=r"(t) : "f"(v));
    return t;
}

__device__ __forceinline__ void mma16n8k8(float* d, const uint32_t* a, const uint32_t* b) {
    asm volatile(
        "mma.sync.aligned.m16n8k8.row.col.f32.tf32.tf32.f32 "
        "{%0,%1,%2,%3}, {%4,%5,%6,%7}, {%8,%9}, {%0,%1,%2,%3};"
        : "+f"(d[0]), "+f"(d[1]), "+f"(d[2]), "+f"(d[3])
        : "r"(a[0]), "r"(a[1]), "r"(a[2]), "r"(a[3]), "r"(b[0]), "r"(b[1]));
}

// 64x64 fp32 tile -> smem tf32, stride 68.
// Lane mapping r=L>>2, c=L&3 makes every STS conflict-free with stride 68.
__device__ __forceinline__ void load_tile_tf32(
    const float* __restrict__ gbase, uint32_t* __restrict__ smem, int tid)
{
    const int L = tid & 31, w = tid >> 5;
    const int r0 = w * 8 + (L >> 2);
    const int c0 = L & 3;
#pragma unroll
    for (int p = 0; p < 2; p++) {
        const int r = r0 + 32 * p;
        const float* grow = gbase + (size_t)r * C3;
        uint32_t* srow = smem + r * 68;
#pragma unroll
        for (int cc = 0; cc < 16; cc++) {
            int c = c0 + 4 * cc;
            srow[c] = f2tf32(grow[c]);
        }
    }
}

#define ATTN_SMEM_WORDS (4 * 64 * 68)
#define ATTN_SMEM_BYTES (ATTN_SMEM_WORDS * 4)   // 69632

__global__ void __launch_bounds__(128) attn_tc_kernel(
    const float* __restrict__ qkv, float* __restrict__ attout)
{
    extern __shared__ uint32_t smu[];
    uint32_t* Qs = smu;                 // [64][68] tf32, row-major [row][k]
    uint32_t* Ks = smu + 64 * 68;       // [64][68]          [key][k]
    uint32_t* Vs = smu + 2 * 64 * 68;   // [64][68]          [key][dim]
    uint32_t* Ps = smu + 3 * 64 * 68;   // [64][68]          [row][key]

    const int qt  = blockIdx.x;
    const int h   = blockIdx.y;
    const int b   = blockIdx.z;
    const int tid = threadIdx.x;
    const int w   = tid >> 5;
    const int L   = tid & 31;
    const int gid = L >> 2;      // 0..7
    const int tig = L & 3;       // 0..3
    const int wrow = w * 16;     // warp's row base within the 64-row tile

    const float* qbase = qkv + (size_t)b * SEQ * C3 + h * HD;
    const float* kbase = qbase + C_EMBED;
    const float* vbase = qbase + 2 * C_EMBED;

    load_tile_tf32(qbase + (size_t)qt * 64 * C3, Qs, tid);

    float o[8][4];
#pragma unroll
    for (int nt = 0; nt < 8; nt++)
#pragma unroll
        for (int e = 0; e < 4; e++) o[nt][e] = 0.f;
    float m0 = -1e30f, m1 = -1e30f, l0 = 0.f, l1 = 0.f;

    for (int j0 = 0; j0 <= qt; j0++) {
        __syncthreads();   // prior iteration's Ks/Vs reads complete
        load_tile_tf32(kbase + (size_t)j0 * 64 * C3, Ks, tid);
        load_tile_tf32(vbase + (size_t)j0 * 64 * C3, Vs, tid);
        __syncthreads();

        // ---- S = Q K^T  (warp: 16 rows x 64 keys = 8 n-tiles) ----
        float s[8][4];
#pragma unroll
        for (int nt = 0; nt < 8; nt++)
#pragma unroll
            for (int e = 0; e < 4; e++) s[nt][e] = 0.f;

#pragma unroll
        for (int ks = 0; ks < 8; ks++) {
            uint32_t qa[4];
            const int rq = (wrow + gid) * 68 + 8 * ks + tig;
            qa[0] = Qs[rq];
            qa[1] = Qs[rq + 8 * 68];
            qa[2] = Qs[rq + 4];
            qa[3] = Qs[rq + 8 * 68 + 4];
#pragma unroll
            for (int nt = 0; nt < 8; nt++) {
                uint32_t kb[2];
                const int rk = (nt * 8 + gid) * 68 + 8 * ks + tig;
                kb[0] = Ks[rk];
                kb[1] = Ks[rk + 4];
                mma16n8k8(s[nt], qa, kb);
            }
        }

        // ---- scale + causal mask (only diagonal tile needs masking) ----
#pragma unroll
        for (int nt = 0; nt < 8; nt++)
#pragma unroll
            for (int e = 0; e < 4; e++) s[nt][e] *= 0.125f;

        if (j0 == qt) {
            const int r0t = wrow + gid;       // in-tile row (c0,c1)
#pragma unroll
            for (int nt = 0; nt < 8; nt++) {
                const int c0t = nt * 8 + 2 * tig;
                if (c0t     > r0t)     s[nt][0] = -1e30f;
                if (c0t + 1 > r0t)     s[nt][1] = -1e30f;
                if (c0t     > r0t + 8) s[nt][2] = -1e30f;
                if (c0t + 1 > r0t + 8) s[nt][3] = -1e30f;
            }
        }

        // ---- online softmax (rows: wrow+gid and wrow+gid+8) ----
        float mloc0 = -1e30f, mloc1 = -1e30f;
#pragma unroll
        for (int nt = 0; nt < 8; nt++) {
            mloc0 = fmaxf(mloc0, fmaxf(s[nt][0], s[nt][1]));
            mloc1 = fmaxf(mloc1, fmaxf(s[nt][2], s[nt][3]));
        }
        mloc0 = fmaxf(mloc0, __shfl_xor_sync(0xffffffffu, mloc0, 1));
        mloc0 = fmaxf(mloc0, __shfl_xor_sync(0xffffffffu, mloc0, 2));
        mloc1 = fmaxf(mloc1, __shfl_xor_sync(0xffffffffu, mloc1, 1));
        mloc1 = fmaxf(mloc1, __shfl_xor_sync(0xffffffffu, mloc1, 2));

        const float mn0 = fmaxf(m0, mloc0);
        const float mn1 = fmaxf(m1, mloc1);
        const float cr0 = __expf(m0 - mn0);
        const float cr1 = __expf(m1 - mn1);

        float rs0 = 0.f, rs1 = 0.f;
#pragma unroll
        for (int nt = 0; nt < 8; nt++) {
            s[nt][0] = __expf(s[nt][0] - mn0);
            s[nt][1] = __expf(s[nt][1] - mn0);
            s[nt][2] = __expf(s[nt][2] - mn1);
            s[nt][3] = __expf(s[nt][3] - mn1);
            rs0 += s[nt][0] + s[nt][1];
            rs1 += s[nt][2] + s[nt][3];
        }
        rs0 += __shfl_xor_sync(0xffffffffu, rs0, 1);
        rs0 += __shfl_xor_sync(0xffffffffu, rs0, 2);
        rs1 += __shfl_xor_sync(0xffffffffu, rs1, 1);
        rs1 += __shfl_xor_sync(0xffffffffu, rs1, 2);

        l0 = l0 * cr0 + rs0;
        l1 = l1 * cr1 + rs1;
        m0 = mn0;
        m1 = mn1;
#pragma unroll
        for (int nt = 0; nt < 8; nt++) {
            o[nt][0] *= cr0; o[nt][1] *= cr0;
            o[nt][2] *= cr1; o[nt][3] *= cr1;
        }

        // ---- stage P to smem (warp-private rows) ----
#pragma unroll
        for (int nt = 0; nt < 8; nt++) {
            const int pb = (wrow + gid) * 68 + nt * 8 + 2 * tig;
            Ps[pb]              = f2tf32(s[nt][0]);
            Ps[pb + 1]          = f2tf32(s[nt][1]);
            Ps[pb + 8 * 68]     = f2tf32(s[nt][2]);
            Ps[pb + 8 * 68 + 1] = f2tf32(s[nt][3]);
        }
        __syncwarp();

        // ---- O += P V  (n-tiles over dim) ----
#pragma unroll
        for (int ks = 0; ks < 8; ks++) {
            uint32_t pa[4];
            const int rp = (wrow + gid) * 68 + 8 * ks + tig;
            pa[0] = Ps[rp];
            pa[1] = Ps[rp + 8 * 68];
            pa[2] = Ps[rp + 4];
            pa[3] = Ps[rp + 8 * 68 + 4];
#pragma unroll
            for (int nt = 0; nt < 8; nt++) {
                uint32_t vb[2];
                const int rv = (8 * ks + tig) * 68 + nt * 8 + gid;
                vb[0] = Vs[rv];
                vb[1] = Vs[rv + 4 * 68];
                mma16n8k8(o[nt], pa, vb);
            }
        }
        __syncwarp();   // Ps reads done before next iter's P store
    }

    // ---- normalize + write [b, t, h*64 + dim] ----
    const float inv0 = 1.f / l0;
    const float inv1 = 1.f / l1;
    const int t0 = qt * 64 + wrow + gid;
#pragma unroll
    for (int nt = 0; nt < 8; nt++) {
        const int d = h * HD + nt * 8 + 2 * tig;
        float2 v0 = make_float2(o[nt][0] * inv0, o[nt][1] * inv0);
        *(float2*)&attout[(size_t)(b * SEQ + t0) * C_EMBED + d] = v0;
        float2 v1 = make_float2(o[nt][2] * inv1, o[nt][3] * inv1);
        *(float2*)&attout[(size_t)(b * SEQ + t0 + 8) * C_EMBED + d] = v1;
    }
}

// ---------------------------------------------------------------------------
extern "C" void kernel_launch(void* const* d_in, const int* in_sizes, int n_in,
                              void* d_out, int out_size)
{
    const float* x     = (const float*)d_in[0];
    const float* Wqkv  = (const float*)d_in[1];
    const float* bqkv  = (const float*)d_in[2];
    const float* Wproj = (const float*)d_in[3];
    const float* bproj = (const float*)d_in[4];
    float* out = (float*)d_out;

    float *qkv, *att;
    cudaGetSymbolAddress((void**)&qkv, g_qkv);
    cudaGetSymbolAddress((void**)&att, g_att);

    cudaFuncSetAttribute(attn_tc_kernel, cudaFuncAttributeMaxDynamicSharedMemorySize,
                         ATTN_SMEM_BYTES);

    // 1) QKV projection: [8192,768] @ [768,2304] + b
    dim3 g1(C3 / 128, MROWS / 128);
    gemm_bias_kernel<<<g1, 256>>>(x, Wqkv, bqkv, qkv, MROWS, C3, C_EMBED);

    // 2) Causal flash attention (tf32 mma.sync)
    dim3 g2(SEQ / 64, NH, BATCH);
    attn_tc_kernel<<<g2, 128, ATTN_SMEM_BYTES>>>(qkv, att);

    // 3) Output projection: [8192,768] @ [768,768] + b
    dim3 g3(C_EMBED / 128, MROWS / 128);
    gemm_bias_kernel<<<g3, 256>>>(att, Wproj, bproj, out, MROWS, C_EMBED, C_EMBED);
}

// round 4
// speedup vs baseline: 1.9527x; 1.3766x over previous
#include <cuda_runtime.h>
#include <math.h>
#include <stdint.h>

#define C_EMBED 768
#define NH 12
#define HD 64
#define BATCH 2
#define SEQ 4096
#define MROWS (BATCH*SEQ)        // 8192
#define C3 (3*C_EMBED)           // 2304

// Scratch (no allocations allowed)
__device__ float g_qkv[(size_t)MROWS * C3];       // 75.5 MB
__device__ float g_att[(size_t)MROWS * C_EMBED];  // 25 MB

// ---------------------------------------------------------------------------
// tf32 helpers
// ---------------------------------------------------------------------------
__device__ __forceinline__ uint32_t f2tf32(float v) {
    uint32_t t;
    asm("cvt.rna.tf32.f32 %0, %1;" : "=r"(t) : "f"(v));
    return t;
}

__device__ __forceinline__ void mma16n8k8(float* d, const uint32_t* a, const uint32_t* b) {
    asm volatile(
        "mma.sync.aligned.m16n8k8.row.col.f32.tf32.tf32.f32 "
        "{%0,%1,%2,%3}, {%4,%5,%6,%7}, {%8,%9}, {%0,%1,%2,%3};"
        : "+f"(d[0]), "+f"(d[1]), "+f"(d[2]), "+f"(d[3])
        : "r"(a[0]), "r"(a[1]), "r"(a[2]), "r"(a[3]), "r"(b[0]), "r"(b[1]));
}

// ===========================================================================
// tf32 mma GEMM: C[M,N] = A[M,K] @ B[K,N] + bias[N]
// CTA tile 128x128, BK=32, 256 threads = 8 warps (warp tile 64m x 32n).
// Smem tiles XOR-swizzled at float4 granularity: float k of row r lives at
//   r*32 + (k ^ ((r&7)*4))   -> conflict-free STS.128 and fragment LDS.
// B is stored transposed (n-major) via per-thread 4x strided LDG gather.
// ===========================================================================
__global__ void __launch_bounds__(256) gemm_tf32_kernel(
    const float* __restrict__ A, const float* __restrict__ Bm,
    const float* __restrict__ bias, float* __restrict__ Cm,
    int M, int N, int K)
{
    __shared__ uint32_t As[128 * 32];   // 16 KB
    __shared__ uint32_t Bs[128 * 32];   // 16 KB  (B^T: [n][k])

    const int tid = threadIdx.x;
    const int w   = tid >> 5;
    const int L   = tid & 31;
    const int gid = L >> 2;     // 0..7
    const int tig = L & 3;      // 0..3
    const int row0 = blockIdx.y * 128;
    const int col0 = blockIdx.x * 128;
    const int m0w = (w & 1) * 64;     // warp row base
    const int n0w = (w >> 1) * 32;    // warp col base

    float acc[4][4][4];
#pragma unroll
    for (int mt = 0; mt < 4; mt++)
#pragma unroll
        for (int nt = 0; nt < 4; nt++)
#pragma unroll
            for (int e = 0; e < 4; e++) acc[mt][nt][e] = 0.f;

    uint4* As4 = (uint4*)As;
    uint4* Bs4 = (uint4*)Bs;

    for (int kb = 0; kb < K; kb += 32) {
        __syncthreads();   // previous iteration's fragment reads complete

        // ---- A tile: 128 rows x 32 k (row-major gmem, coalesced float4) ----
#pragma unroll
        for (int u = 0; u < 4; u++) {
            int fid = u * 256 + tid;        // 0..1023
            int r   = fid >> 3;             // 0..127
            int c4  = fid & 7;              // 0..7
            float4 v = *(const float4*)&A[(size_t)(row0 + r) * K + kb + c4 * 4];
            uint4 t;
            t.x = f2tf32(v.x); t.y = f2tf32(v.y);
            t.z = f2tf32(v.z); t.w = f2tf32(v.w);
            As4[r * 8 + (c4 ^ (r & 7))] = t;
        }
        // ---- B tile -> B^T[n][k]: 4x strided-coalesced LDG gather ----
#pragma unroll
        for (int u = 0; u < 4; u++) {
            int fid = u * 256 + tid;        // 0..1023
            int n   = fid & 127;            // 0..127
            int k4  = fid >> 7;             // 0..7
            const float* bp = &Bm[(size_t)(kb + k4 * 4) * N + col0 + n];
            uint4 t;
            t.x = f2tf32(bp[0]);
            t.y = f2tf32(bp[(size_t)N]);
            t.z = f2tf32(bp[(size_t)2 * N]);
            t.w = f2tf32(bp[(size_t)3 * N]);
            Bs4[n * 8 + (k4 ^ (n & 7))] = t;
        }
        __syncthreads();

        // ---- mma over 4 k-steps of 8 ----
#pragma unroll
        for (int ks = 0; ks < 4; ks++) {
            const int k0 = ks * 8;
            uint32_t af[4][4];
#pragma unroll
            for (int mt = 0; mt < 4; mt++) {
                const int r = m0w + mt * 16 + gid;
                const int x0 = (k0 + tig) ^ (gid * 4);
                const int x4 = (k0 + tig + 4) ^ (gid * 4);
                af[mt][0] = As[r * 32 + x0];
                af[mt][1] = As[(r + 8) * 32 + x0];
                af[mt][2] = As[r * 32 + x4];
                af[mt][3] = As[(r + 8) * 32 + x4];
            }
            uint32_t bf[4][2];
#pragma unroll
            for (int nt = 0; nt < 4; nt++) {
                const int n = n0w + nt * 8 + gid;
                const int x0 = (k0 + tig) ^ (gid * 4);
                const int x4 = (k0 + tig + 4) ^ (gid * 4);
                bf[nt][0] = Bs[n * 32 + x0];
                bf[nt][1] = Bs[n * 32 + x4];
            }
#pragma unroll
            for (int mt = 0; mt < 4; mt++)
#pragma unroll
                for (int nt = 0; nt < 4; nt++)
                    mma16n8k8(acc[mt][nt], af[mt], bf[nt]);
        }
    }

    // ---- epilogue: bias + direct float2 stores ----
#pragma unroll
    for (int mt = 0; mt < 4; mt++) {
        const int r = row0 + m0w + mt * 16 + gid;
#pragma unroll
        for (int nt = 0; nt < 4; nt++) {
            const int c = col0 + n0w + nt * 8 + 2 * tig;
            const float b0 = bias[c], b1 = bias[c + 1];
            float2 v0 = make_float2(acc[mt][nt][0] + b0, acc[mt][nt][1] + b1);
            *(float2*)&Cm[(size_t)r * N + c] = v0;
            float2 v1 = make_float2(acc[mt][nt][2] + b0, acc[mt][nt][3] + b1);
            *(float2*)&Cm[(size_t)(r + 8) * N + c] = v1;
        }
    }
}

// ===========================================================================
// tf32 mma.sync flash attention (causal) — verified R3 kernel, unchanged.
// ===========================================================================
__device__ __forceinline__ void load_tile_tf32(
    const float* __restrict__ gbase, uint32_t* __restrict__ smem, int tid)
{
    const int L = tid & 31, w = tid >> 5;
    const int r0 = w * 8 + (L >> 2);
    const int c0 = L & 3;
#pragma unroll
    for (int p = 0; p < 2; p++) {
        const int r = r0 + 32 * p;
        const float* grow = gbase + (size_t)r * C3;
        uint32_t* srow = smem + r * 68;
#pragma unroll
        for (int cc = 0; cc < 16; cc++) {
            int c = c0 + 4 * cc;
            srow[c] = f2tf32(grow[c]);
        }
    }
}

#define ATTN_SMEM_WORDS (4 * 64 * 68)
#define ATTN_SMEM_BYTES (ATTN_SMEM_WORDS * 4)   // 69632

__global__ void __launch_bounds__(128) attn_tc_kernel(
    const float* __restrict__ qkv, float* __restrict__ attout)
{
    extern __shared__ uint32_t smu[];
    uint32_t* Qs = smu;
    uint32_t* Ks = smu + 64 * 68;
    uint32_t* Vs = smu + 2 * 64 * 68;
    uint32_t* Ps = smu + 3 * 64 * 68;

    const int qt  = blockIdx.x;
    const int h   = blockIdx.y;
    const int b   = blockIdx.z;
    const int tid = threadIdx.x;
    const int w   = tid >> 5;
    const int L   = tid & 31;
    const int gid = L >> 2;
    const int tig = L & 3;
    const int wrow = w * 16;

    const float* qbase = qkv + (size_t)b * SEQ * C3 + h * HD;
    const float* kbase = qbase + C_EMBED;
    const float* vbase = qbase + 2 * C_EMBED;

    load_tile_tf32(qbase + (size_t)qt * 64 * C3, Qs, tid);

    float o[8][4];
#pragma unroll
    for (int nt = 0; nt < 8; nt++)
#pragma unroll
        for (int e = 0; e < 4; e++) o[nt][e] = 0.f;
    float m0 = -1e30f, m1 = -1e30f, l0 = 0.f, l1 = 0.f;

    for (int j0 = 0; j0 <= qt; j0++) {
        __syncthreads();
        load_tile_tf32(kbase + (size_t)j0 * 64 * C3, Ks, tid);
        load_tile_tf32(vbase + (size_t)j0 * 64 * C3, Vs, tid);
        __syncthreads();

        float s[8][4];
#pragma unroll
        for (int nt = 0; nt < 8; nt++)
#pragma unroll
            for (int e = 0; e < 4; e++) s[nt][e] = 0.f;

#pragma unroll
        for (int ks = 0; ks < 8; ks++) {
            uint32_t qa[4];
            const int rq = (wrow + gid) * 68 + 8 * ks + tig;
            qa[0] = Qs[rq];
            qa[1] = Qs[rq + 8 * 68];
            qa[2] = Qs[rq + 4];
            qa[3] = Qs[rq + 8 * 68 + 4];
#pragma unroll
            for (int nt = 0; nt < 8; nt++) {
                uint32_t kb[2];
                const int rk = (nt * 8 + gid) * 68 + 8 * ks + tig;
                kb[0] = Ks[rk];
                kb[1] = Ks[rk + 4];
                mma16n8k8(s[nt], qa, kb);
            }
        }

#pragma unroll
        for (int nt = 0; nt < 8; nt++)
#pragma unroll
            for (int e = 0; e < 4; e++) s[nt][e] *= 0.125f;

        if (j0 == qt) {
            const int r0t = wrow + gid;
#pragma unroll
            for (int nt = 0; nt < 8; nt++) {
                const int c0t = nt * 8 + 2 * tig;
                if (c0t     > r0t)     s[nt][0] = -1e30f;
                if (c0t + 1 > r0t)     s[nt][1] = -1e30f;
                if (c0t     > r0t + 8) s[nt][2] = -1e30f;
                if (c0t + 1 > r0t + 8) s[nt][3] = -1e30f;
            }
        }

        float mloc0 = -1e30f, mloc1 = -1e30f;
#pragma unroll
        for (int nt = 0; nt < 8; nt++) {
            mloc0 = fmaxf(mloc0, fmaxf(s[nt][0], s[nt][1]));
            mloc1 = fmaxf(mloc1, fmaxf(s[nt][2], s[nt][3]));
        }
        mloc0 = fmaxf(mloc0, __shfl_xor_sync(0xffffffffu, mloc0, 1));
        mloc0 = fmaxf(mloc0, __shfl_xor_sync(0xffffffffu, mloc0, 2));
        mloc1 = fmaxf(mloc1, __shfl_xor_sync(0xffffffffu, mloc1, 1));
        mloc1 = fmaxf(mloc1, __shfl_xor_sync(0xffffffffu, mloc1, 2));

        const float mn0 = fmaxf(m0, mloc0);
        const float mn1 = fmaxf(m1, mloc1);
        const float cr0 = __expf(m0 - mn0);
        const float cr1 = __expf(m1 - mn1);

        float rs0 = 0.f, rs1 = 0.f;
#pragma unroll
        for (int nt = 0; nt < 8; nt++) {
            s[nt][0] = __expf(s[nt][0] - mn0);
            s[nt][1] = __expf(s[nt][1] - mn0);
            s[nt][2] = __expf(s[nt][2] - mn1);
            s[nt][3] = __expf(s[nt][3] - mn1);
            rs0 += s[nt][0] + s[nt][1];
            rs1 += s[nt][2] + s[nt][3];
        }
        rs0 += __shfl_xor_sync(0xffffffffu, rs0, 1);
        rs0 += __shfl_xor_sync(0xffffffffu, rs0, 2);
        rs1 += __shfl_xor_sync(0xffffffffu, rs1, 1);
        rs1 += __shfl_xor_sync(0xffffffffu, rs1, 2);

        l0 = l0 * cr0 + rs0;
        l1 = l1 * cr1 + rs1;
        m0 = mn0;
        m1 = mn1;
#pragma unroll
        for (int nt = 0; nt < 8; nt++) {
            o[nt][0] *= cr0; o[nt][1] *= cr0;
            o[nt][2] *= cr1; o[nt][3] *= cr1;
        }

#pragma unroll
        for (int nt = 0; nt < 8; nt++) {
            const int pb = (wrow + gid) * 68 + nt * 8 + 2 * tig;
            Ps[pb]              = f2tf32(s[nt][0]);
            Ps[pb + 1]          = f2tf32(s[nt][1]);
            Ps[pb + 8 * 68]     = f2tf32(s[nt][2]);
            Ps[pb + 8 * 68 + 1] = f2tf32(s[nt][3]);
        }
        __syncwarp();

#pragma unroll
        for (int ks = 0; ks < 8; ks++) {
            uint32_t pa[4];
            const int rp = (wrow + gid) * 68 + 8 * ks + tig;
            pa[0] = Ps[rp];
            pa[1] = Ps[rp + 8 * 68];
            pa[2] = Ps[rp + 4];
            pa[3] = Ps[rp + 8 * 68 + 4];
#pragma unroll
            for (int nt = 0; nt < 8; nt++) {
                uint32_t vb[2];
                const int rv = (8 * ks + tig) * 68 + nt * 8 + gid;
                vb[0] = Vs[rv];
                vb[1] = Vs[rv + 4 * 68];
                mma16n8k8(o[nt], pa, vb);
            }
        }
        __syncwarp();
    }

    const float inv0 = 1.f / l0;
    const float inv1 = 1.f / l1;
    const int t0 = qt * 64 + wrow + gid;
#pragma unroll
    for (int nt = 0; nt < 8; nt++) {
        const int d = h * HD + nt * 8 + 2 * tig;
        float2 v0 = make_float2(o[nt][0] * inv0, o[nt][1] * inv0);
        *(float2*)&attout[(size_t)(b * SEQ + t0) * C_EMBED + d] = v0;
        float2 v1 = make_float2(o[nt][2] * inv1, o[nt][3] * inv1);
        *(float2*)&attout[(size_t)(b * SEQ + t0 + 8) * C_EMBED + d] = v1;
    }
}

// ---------------------------------------------------------------------------
extern "C" void kernel_launch(void* const* d_in, const int* in_sizes, int n_in,
                              void* d_out, int out_size)
{
    const float* x     = (const float*)d_in[0];
    const float* Wqkv  = (const float*)d_in[1];
    const float* bqkv  = (const float*)d_in[2];
    const float* Wproj = (const float*)d_in[3];
    const float* bproj = (const float*)d_in[4];
    float* out = (float*)d_out;

    float *qkv, *att;
    cudaGetSymbolAddress((void**)&qkv, g_qkv);
    cudaGetSymbolAddress((void**)&att, g_att);

    cudaFuncSetAttribute(attn_tc_kernel, cudaFuncAttributeMaxDynamicSharedMemorySize,
                         ATTN_SMEM_BYTES);

    // 1) QKV projection: [8192,768] @ [768,2304] + b
    dim3 g1(C3 / 128, MROWS / 128);
    gemm_tf32_kernel<<<g1, 256>>>(x, Wqkv, bqkv, qkv, MROWS, C3, C_EMBED);

    // 2) Causal flash attention (tf32 mma.sync)
    dim3 g2(SEQ / 64, NH, BATCH);
    attn_tc_kernel<<<g2, 128, ATTN_SMEM_BYTES>>>(qkv, att);

    // 3) Output projection: [8192,768] @ [768,768] + b
    dim3 g3(C_EMBED / 128, MROWS / 128);
    gemm_tf32_kernel<<<g3, 256>>>(att, Wproj, bproj, out, MROWS, C_EMBED, C_EMBED);
}

// round 5
// speedup vs baseline: 2.1448x; 1.0984x over previous
#include <cuda_runtime.h>
#include <math.h>
#include <stdint.h>

#define C_EMBED 768
#define NH 12
#define HD 64
#define BATCH 2
#define SEQ 4096
#define MROWS (BATCH*SEQ)        // 8192
#define C3 (3*C_EMBED)           // 2304

// Scratch (no allocations allowed)
__device__ float g_qkv[(size_t)MROWS * C3];       // 75.5 MB
__device__ float g_att[(size_t)MROWS * C_EMBED];  // 25 MB

// ---------------------------------------------------------------------------
// tf32 helpers
// ---------------------------------------------------------------------------
__device__ __forceinline__ uint32_t f2tf32(float v) {
    uint32_t t;
    asm("cvt.rna.tf32.f32 %0, %1;" : "=r"(t) : "f"(v));
    return t;
}

__device__ __forceinline__ void mma16n8k8(float* d, const uint32_t* a, const uint32_t* b) {
    asm volatile(
        "mma.sync.aligned.m16n8k8.row.col.f32.tf32.tf32.f32 "
        "{%0,%1,%2,%3}, {%4,%5,%6,%7}, {%8,%9}, {%0,%1,%2,%3};"
        : "+f"(d[0]), "+f"(d[1]), "+f"(d[2]), "+f"(d[3])
        : "r"(a[0]), "r"(a[1]), "r"(a[2]), "r"(a[3]), "r"(b[0]), "r"(b[1]));
}

// ===========================================================================
// tf32 mma GEMM (verified R4 kernel, unchanged): C = A@B + bias
// ===========================================================================
__global__ void __launch_bounds__(256) gemm_tf32_kernel(
    const float* __restrict__ A, const float* __restrict__ Bm,
    const float* __restrict__ bias, float* __restrict__ Cm,
    int M, int N, int K)
{
    __shared__ uint32_t As[128 * 32];
    __shared__ uint32_t Bs[128 * 32];

    const int tid = threadIdx.x;
    const int w   = tid >> 5;
    const int L   = tid & 31;
    const int gid = L >> 2;
    const int tig = L & 3;
    const int row0 = blockIdx.y * 128;
    const int col0 = blockIdx.x * 128;
    const int m0w = (w & 1) * 64;
    const int n0w = (w >> 1) * 32;

    float acc[4][4][4];
#pragma unroll
    for (int mt = 0; mt < 4; mt++)
#pragma unroll
        for (int nt = 0; nt < 4; nt++)
#pragma unroll
            for (int e = 0; e < 4; e++) acc[mt][nt][e] = 0.f;

    uint4* As4 = (uint4*)As;
    uint4* Bs4 = (uint4*)Bs;

    for (int kb = 0; kb < K; kb += 32) {
        __syncthreads();
#pragma unroll
        for (int u = 0; u < 4; u++) {
            int fid = u * 256 + tid;
            int r   = fid >> 3;
            int c4  = fid & 7;
            float4 v = *(const float4*)&A[(size_t)(row0 + r) * K + kb + c4 * 4];
            uint4 t;
            t.x = f2tf32(v.x); t.y = f2tf32(v.y);
            t.z = f2tf32(v.z); t.w = f2tf32(v.w);
            As4[r * 8 + (c4 ^ (r & 7))] = t;
        }
#pragma unroll
        for (int u = 0; u < 4; u++) {
            int fid = u * 256 + tid;
            int n   = fid & 127;
            int k4  = fid >> 7;
            const float* bp = &Bm[(size_t)(kb + k4 * 4) * N + col0 + n];
            uint4 t;
            t.x = f2tf32(bp[0]);
            t.y = f2tf32(bp[(size_t)N]);
            t.z = f2tf32(bp[(size_t)2 * N]);
            t.w = f2tf32(bp[(size_t)3 * N]);
            Bs4[n * 8 + (k4 ^ (n & 7))] = t;
        }
        __syncthreads();

#pragma unroll
        for (int ks = 0; ks < 4; ks++) {
            const int k0 = ks * 8;
            uint32_t af[4][4];
#pragma unroll
            for (int mt = 0; mt < 4; mt++) {
                const int r = m0w + mt * 16 + gid;
                const int x0 = (k0 + tig) ^ (gid * 4);
                const int x4 = (k0 + tig + 4) ^ (gid * 4);
                af[mt][0] = As[r * 32 + x0];
                af[mt][1] = As[(r + 8) * 32 + x0];
                af[mt][2] = As[r * 32 + x4];
                af[mt][3] = As[(r + 8) * 32 + x4];
            }
            uint32_t bf[4][2];
#pragma unroll
            for (int nt = 0; nt < 4; nt++) {
                const int n = n0w + nt * 8 + gid;
                const int x0 = (k0 + tig) ^ (gid * 4);
                const int x4 = (k0 + tig + 4) ^ (gid * 4);
                bf[nt][0] = Bs[n * 32 + x0];
                bf[nt][1] = Bs[n * 32 + x4];
            }
#pragma unroll
            for (int mt = 0; mt < 4; mt++)
#pragma unroll
                for (int nt = 0; nt < 4; nt++)
                    mma16n8k8(acc[mt][nt], af[mt], bf[nt]);
        }
    }

#pragma unroll
    for (int mt = 0; mt < 4; mt++) {
        const int r = row0 + m0w + mt * 16 + gid;
#pragma unroll
        for (int nt = 0; nt < 4; nt++) {
            const int c = col0 + n0w + nt * 8 + 2 * tig;
            const float b0 = bias[c], b1 = bias[c + 1];
            float2 v0 = make_float2(acc[mt][nt][0] + b0, acc[mt][nt][1] + b1);
            *(float2*)&Cm[(size_t)r * N + c] = v0;
            float2 v1 = make_float2(acc[mt][nt][2] + b0, acc[mt][nt][3] + b1);
            *(float2*)&Cm[(size_t)(r + 8) * N + c] = v1;
        }
    }
}

// ===========================================================================
// tf32 mma.sync flash attention (causal), 128-row query tiles.
// 256 threads = 8 warps; warp owns 16 query rows (verified R3 warp structure).
// Q staged once per CTA (scale folded in); K/V tiles amortized over 128 rows.
// ===========================================================================
#define ATTN_SMEM_WORDS ((128 + 64 + 64 + 128) * 68)
#define ATTN_SMEM_BYTES (ATTN_SMEM_WORDS * 4)   // 104448

__global__ void __launch_bounds__(256) attn_tc_kernel(
    const float* __restrict__ qkv, float* __restrict__ attout)
{
    extern __shared__ uint32_t smu[];
    uint32_t* Qs = smu;                    // [128][68]  [row][k], pre-scaled
    uint32_t* Ks = smu + 128 * 68;         // [64][68]   [key][k]
    uint32_t* Vs = smu + 192 * 68;         // [64][68]   [key][dim]
    uint32_t* Ps = smu + 256 * 68;         // [128][68]  [row][key]

    const int qt  = blockIdx.x;            // 128-row query tile (0..31)
    const int h   = blockIdx.y;
    const int b   = blockIdx.z;
    const int tid = threadIdx.x;
    const int w   = tid >> 5;
    const int L   = tid & 31;
    const int gid = L >> 2;
    const int tig = L & 3;
    const int wrow = w * 16;               // warp row base within 128

    const float* qbase = qkv + (size_t)b * SEQ * C3 + h * HD;
    const float* kbase = qbase + C_EMBED;
    const float* vbase = qbase + 2 * C_EMBED;

    // ---- stage Q (128 x 64), scale folded before tf32 rounding ----
    {
        const int r0 = w * 8 + (L >> 2);   // 0..63
        const int c0 = L & 3;
#pragma unroll
        for (int p = 0; p < 2; p++) {
            const int r = r0 + 64 * p;
            const float* grow = qbase + (size_t)(qt * 128 + r) * C3;
            uint32_t* srow = Qs + r * 68;
#pragma unroll
            for (int cc = 0; cc < 16; cc++) {
                int c = c0 + 4 * cc;
                srow[c] = f2tf32(grow[c] * 0.125f);
            }
        }
    }

    float o[8][4];
#pragma unroll
    for (int nt = 0; nt < 8; nt++)
#pragma unroll
        for (int e = 0; e < 4; e++) o[nt][e] = 0.f;
    float m0 = -1e30f, m1 = -1e30f, l0 = 0.f, l1 = 0.f;

    const int rmax_w = qt * 128 + wrow + 15;   // warp's last query row
    const int ntiles = 2 * qt + 2;             // key tiles of 64

    for (int j0 = 0; j0 < ntiles; j0++) {
        __syncthreads();   // prior iteration's Ks/Vs reads complete
        // ---- load K/V tile (64 x 64) ----
        {
            const int r  = w * 8 + (L >> 2);   // 0..63
            const int c0 = L & 3;
            const float* krow = kbase + (size_t)(j0 * 64 + r) * C3;
            const float* vrow = vbase + (size_t)(j0 * 64 + r) * C3;
            uint32_t* ks = Ks + r * 68;
            uint32_t* vs = Vs + r * 68;
#pragma unroll
            for (int cc = 0; cc < 16; cc++) {
                int c = c0 + 4 * cc;
                ks[c] = f2tf32(krow[c]);
                vs[c] = f2tf32(vrow[c]);
            }
        }
        __syncthreads();

        if (j0 * 64 > rmax_w) continue;   // tile fully in the future for this warp

        // ---- S = Q K^T ----
        float s[8][4];
#pragma unroll
        for (int nt = 0; nt < 8; nt++)
#pragma unroll
            for (int e = 0; e < 4; e++) s[nt][e] = 0.f;

#pragma unroll
        for (int ks = 0; ks < 8; ks++) {
            uint32_t qa[4];
            const int rq = (wrow + gid) * 68 + 8 * ks + tig;
            qa[0] = Qs[rq];
            qa[1] = Qs[rq + 8 * 68];
            qa[2] = Qs[rq + 4];
            qa[3] = Qs[rq + 8 * 68 + 4];
#pragma unroll
            for (int nt = 0; nt < 8; nt++) {
                uint32_t kb[2];
                const int rk = (nt * 8 + gid) * 68 + 8 * ks + tig;
                kb[0] = Ks[rk];
                kb[1] = Ks[rk + 4];
                mma16n8k8(s[nt], qa, kb);
            }
        }

        // ---- causal mask (only when tile overlaps this warp's diagonal) ----
        const int qr0 = qt * 128 + wrow + gid;     // global row (c0,c1)
        if (j0 * 64 + 63 > qt * 128 + wrow) {
#pragma unroll
            for (int nt = 0; nt < 8; nt++) {
                const int c0g = j0 * 64 + nt * 8 + 2 * tig;
                if (c0g     > qr0)     s[nt][0] = -1e30f;
                if (c0g + 1 > qr0)     s[nt][1] = -1e30f;
                if (c0g     > qr0 + 8) s[nt][2] = -1e30f;
                if (c0g + 1 > qr0 + 8) s[nt][3] = -1e30f;
            }
        }

        // ---- online softmax ----
        float mloc0 = -1e30f, mloc1 = -1e30f;
#pragma unroll
        for (int nt = 0; nt < 8; nt++) {
            mloc0 = fmaxf(mloc0, fmaxf(s[nt][0], s[nt][1]));
            mloc1 = fmaxf(mloc1, fmaxf(s[nt][2], s[nt][3]));
        }
        mloc0 = fmaxf(mloc0, __shfl_xor_sync(0xffffffffu, mloc0, 1));
        mloc0 = fmaxf(mloc0, __shfl_xor_sync(0xffffffffu, mloc0, 2));
        mloc1 = fmaxf(mloc1, __shfl_xor_sync(0xffffffffu, mloc1, 1));
        mloc1 = fmaxf(mloc1, __shfl_xor_sync(0xffffffffu, mloc1, 2));

        const float mn0 = fmaxf(m0, mloc0);
        const float mn1 = fmaxf(m1, mloc1);
        const float cr0 = __expf(m0 - mn0);
        const float cr1 = __expf(m1 - mn1);

        float rs0 = 0.f, rs1 = 0.f;
#pragma unroll
        for (int nt = 0; nt < 8; nt++) {
            s[nt][0] = __expf(s[nt][0] - mn0);
            s[nt][1] = __expf(s[nt][1] - mn0);
            s[nt][2] = __expf(s[nt][2] - mn1);
            s[nt][3] = __expf(s[nt][3] - mn1);
            rs0 += s[nt][0] + s[nt][1];
            rs1 += s[nt][2] + s[nt][3];
        }
        rs0 += __shfl_xor_sync(0xffffffffu, rs0, 1);
        rs0 += __shfl_xor_sync(0xffffffffu, rs0, 2);
        rs1 += __shfl_xor_sync(0xffffffffu, rs1, 1);
        rs1 += __shfl_xor_sync(0xffffffffu, rs1, 2);

        l0 = l0 * cr0 + rs0;
        l1 = l1 * cr1 + rs1;
        m0 = mn0;
        m1 = mn1;
#pragma unroll
        for (int nt = 0; nt < 8; nt++) {
            o[nt][0] *= cr0; o[nt][1] *= cr0;
            o[nt][2] *= cr1; o[nt][3] *= cr1;
        }

        // ---- stage P (warp-private rows) ----
#pragma unroll
        for (int nt = 0; nt < 8; nt++) {
            const int pb = (wrow + gid) * 68 + nt * 8 + 2 * tig;
            Ps[pb]              = f2tf32(s[nt][0]);
            Ps[pb + 1]          = f2tf32(s[nt][1]);
            Ps[pb + 8 * 68]     = f2tf32(s[nt][2]);
            Ps[pb + 8 * 68 + 1] = f2tf32(s[nt][3]);
        }
        __syncwarp();

        // ---- O += P V ----
#pragma unroll
        for (int ks = 0; ks < 8; ks++) {
            uint32_t pa[4];
            const int rp = (wrow + gid) * 68 + 8 * ks + tig;
            pa[0] = Ps[rp];
            pa[1] = Ps[rp + 8 * 68];
            pa[2] = Ps[rp + 4];
            pa[3] = Ps[rp + 8 * 68 + 4];
#pragma unroll
            for (int nt = 0; nt < 8; nt++) {
                uint32_t vb[2];
                const int rv = (8 * ks + tig) * 68 + nt * 8 + gid;
                vb[0] = Vs[rv];
                vb[1] = Vs[rv + 4 * 68];
                mma16n8k8(o[nt], pa, vb);
            }
        }
        __syncwarp();
    }

    // ---- normalize + write ----
    const float inv0 = 1.f / l0;
    const float inv1 = 1.f / l1;
    const int t0 = qt * 128 + wrow + gid;
#pragma unroll
    for (int nt = 0; nt < 8; nt++) {
        const int d = h * HD + nt * 8 + 2 * tig;
        float2 v0 = make_float2(o[nt][0] * inv0, o[nt][1] * inv0);
        *(float2*)&attout[(size_t)(b * SEQ + t0) * C_EMBED + d] = v0;
        float2 v1 = make_float2(o[nt][2] * inv1, o[nt][3] * inv1);
        *(float2*)&attout[(size_t)(b * SEQ + t0 + 8) * C_EMBED + d] = v1;
    }
}

// ---------------------------------------------------------------------------
extern "C" void kernel_launch(void* const* d_in, const int* in_sizes, int n_in,
                              void* d_out, int out_size)
{
    const float* x     = (const float*)d_in[0];
    const float* Wqkv  = (const float*)d_in[1];
    const float* bqkv  = (const float*)d_in[2];
    const float* Wproj = (const float*)d_in[3];
    const float* bproj = (const float*)d_in[4];
    float* out = (float*)d_out;

    float *qkv, *att;
    cudaGetSymbolAddress((void**)&qkv, g_qkv);
    cudaGetSymbolAddress((void**)&att, g_att);

    cudaFuncSetAttribute(attn_tc_kernel, cudaFuncAttributeMaxDynamicSharedMemorySize,
                         ATTN_SMEM_BYTES);

    // 1) QKV projection
    dim3 g1(C3 / 128, MROWS / 128);
    gemm_tf32_kernel<<<g1, 256>>>(x, Wqkv, bqkv, qkv, MROWS, C3, C_EMBED);

    // 2) Causal flash attention (tf32 mma.sync), 128-row query tiles
    dim3 g2(SEQ / 128, NH, BATCH);
    attn_tc_kernel<<<g2, 256, ATTN_SMEM_BYTES>>>(qkv, att);

    // 3) Output projection
    dim3 g3(C_EMBED / 128, MROWS / 128);
    gemm_tf32_kernel<<<g3, 256>>>(att, Wproj, bproj, out, MROWS, C_EMBED, C_EMBED);
}

// round 6
// speedup vs baseline: 3.2034x; 1.4935x over previous
#include <cuda_runtime.h>
#include <math.h>
#include <stdint.h>

#define C_EMBED 768
#define NH 12
#define HD 64
#define BATCH 2
#define SEQ 4096
#define MROWS (BATCH*SEQ)        // 8192
#define C3 (3*C_EMBED)           // 2304

// Scratch (no allocations allowed)
__device__ float g_qkv[(size_t)MROWS * C3];       // 75.5 MB
__device__ float g_att[(size_t)MROWS * C_EMBED];  // 25 MB

// ---------------------------------------------------------------------------
// helpers
// ---------------------------------------------------------------------------
__device__ __forceinline__ uint32_t f2tf32(float v) {
    uint32_t t;
    asm("cvt.rna.tf32.f32 %0, %1;" : "=r"(t) : "f"(v));
    return t;
}

__device__ __forceinline__ void mma16n8k8(float* d, const uint32_t* a, const uint32_t* b) {
    asm volatile(
        "mma.sync.aligned.m16n8k8.row.col.f32.tf32.tf32.f32 "
        "{%0,%1,%2,%3}, {%4,%5,%6,%7}, {%8,%9}, {%0,%1,%2,%3};"
        : "+f"(d[0]), "+f"(d[1]), "+f"(d[2]), "+f"(d[3])
        : "r"(a[0]), "r"(a[1]), "r"(a[2]), "r"(a[3]), "r"(b[0]), "r"(b[1]));
}

__device__ __forceinline__ uint32_t smem_u32(const void* p) {
    uint32_t a;
    asm("{ .reg .u64 t; cvta.to.shared.u64 t, %1; cvt.u32.u64 %0, t; }"
        : "=r"(a) : "l"(p));
    return a;
}

__device__ __forceinline__ void cp_async16(uint32_t saddr, const void* gptr) {
    asm volatile("cp.async.ca.shared.global [%0], [%1], 16;"
                 :: "r"(saddr), "l"(gptr));
}
__device__ __forceinline__ void cp_commit() {
    asm volatile("cp.async.commit_group;" ::: "memory");
}
__device__ __forceinline__ void cp_wait1() {
    asm volatile("cp.async.wait_group 1;" ::: "memory");
}
__device__ __forceinline__ void cp_wait0() {
    asm volatile("cp.async.wait_group 0;" ::: "memory");
}

// ===========================================================================
// tf32 mma GEMM, cp.async double-buffered: C = A@B + bias
// CTA 128x128, BK=32, 256 threads = 8 warps (warp 64m x 32n).
// Smem raw fp32: A [2][128][36] row-major, B [2][32][136] k-major.
// cvt.rna applied at fragment load.
// ===========================================================================
#define G_AW 36
#define G_BW 136
#define G_ABUF (128 * G_AW)              // words per A buffer
#define G_BBUF (32 * G_BW)               // words per B buffer
#define G_BOFF (2 * G_ABUF)              // B base word offset
#define GEMM_SMEM_BYTES ((2 * G_ABUF + 2 * G_BBUF) * 4)   // 71680

__global__ void __launch_bounds__(256, 2) gemm_tf32_kernel(
    const float* __restrict__ A, const float* __restrict__ Bm,
    const float* __restrict__ bias, float* __restrict__ Cm,
    int M, int N, int K)
{
    extern __shared__ float gsm[];
    const uint32_t sb = smem_u32(gsm);

    const int tid = threadIdx.x;
    const int w   = tid >> 5;
    const int L   = tid & 31;
    const int gid = L >> 2;
    const int tig = L & 3;
    const int row0 = blockIdx.y * 128;
    const int col0 = blockIdx.x * 128;
    const int m0w = (w & 1) * 64;
    const int n0w = (w >> 1) * 32;
    const int nk = K >> 5;

    float acc[4][4][4];
#pragma unroll
    for (int mt = 0; mt < 4; mt++)
#pragma unroll
        for (int nt = 0; nt < 4; nt++)
#pragma unroll
            for (int e = 0; e < 4; e++) acc[mt][nt][e] = 0.f;

    // issue A+B tile t into buffer bf
    auto issue = [&](int t, int bf) {
        const int kb = t * 32;
        // A: 1024 16B chunks, 4/thread
#pragma unroll
        for (int u = 0; u < 4; u++) {
            int fid = u * 256 + tid;
            int r   = fid >> 3;
            int c4  = fid & 7;
            cp_async16(sb + (uint32_t)((bf * G_ABUF + r * G_AW + c4 * 4) * 4),
                       &A[(size_t)(row0 + r) * K + kb + c4 * 4]);
        }
        // B: 1024 16B chunks, 4/thread (k-major, coalesced)
#pragma unroll
        for (int u = 0; u < 4; u++) {
            int fid = u * 256 + tid;
            int k   = fid >> 5;
            int n4  = fid & 31;
            cp_async16(sb + (uint32_t)((G_BOFF + bf * G_BBUF + k * G_BW + n4 * 4) * 4),
                       &Bm[(size_t)(kb + k) * N + col0 + n4 * 4]);
        }
    };

    issue(0, 0);
    cp_commit();

    for (int t = 0; t < nk; t++) {
        const int bf = t & 1;
        if (t + 1 < nk) { issue(t + 1, bf ^ 1); cp_commit(); cp_wait1(); }
        else            { cp_wait0(); }
        __syncthreads();

        const float* Af = gsm + bf * G_ABUF;
        const float* Bf = gsm + G_BOFF + bf * G_BBUF;

#pragma unroll
        for (int ks = 0; ks < 4; ks++) {
            const int k0 = ks * 8;
            uint32_t af[4][4];
#pragma unroll
            for (int mt = 0; mt < 4; mt++) {
                const int r = m0w + mt * 16 + gid;
                af[mt][0] = f2tf32(Af[r * G_AW + k0 + tig]);
                af[mt][1] = f2tf32(Af[(r + 8) * G_AW + k0 + tig]);
                af[mt][2] = f2tf32(Af[r * G_AW + k0 + tig + 4]);
                af[mt][3] = f2tf32(Af[(r + 8) * G_AW + k0 + tig + 4]);
            }
            uint32_t bfr[4][2];
#pragma unroll
            for (int nt = 0; nt < 4; nt++) {
                const int n = n0w + nt * 8 + gid;
                bfr[nt][0] = f2tf32(Bf[(k0 + tig) * G_BW + n]);
                bfr[nt][1] = f2tf32(Bf[(k0 + tig + 4) * G_BW + n]);
            }
#pragma unroll
            for (int mt = 0; mt < 4; mt++)
#pragma unroll
                for (int nt = 0; nt < 4; nt++)
                    mma16n8k8(acc[mt][nt], af[mt], bfr[nt]);
        }
        __syncthreads();   // all warps done with bf before it is overwritten
    }

    // epilogue: bias + float2 stores
#pragma unroll
    for (int mt = 0; mt < 4; mt++) {
        const int r = row0 + m0w + mt * 16 + gid;
#pragma unroll
        for (int nt = 0; nt < 4; nt++) {
            const int c = col0 + n0w + nt * 8 + 2 * tig;
            const float b0 = bias[c], b1 = bias[c + 1];
            float2 v0 = make_float2(acc[mt][nt][0] + b0, acc[mt][nt][1] + b1);
            *(float2*)&Cm[(size_t)r * N + c] = v0;
            float2 v1 = make_float2(acc[mt][nt][2] + b0, acc[mt][nt][3] + b1);
            *(float2*)&Cm[(size_t)(r + 8) * N + c] = v1;
        }
    }
}

// ===========================================================================
// tf32 mma flash attention (causal), 128-row Q tiles, cp.async K/V pipeline.
// 256 threads = 8 warps; warp owns 16 query rows.
// Q fragments live in registers (loaded once, scale folded).
// K raw fp32 [2][64][68], V raw fp32 [2][64][72], P tf32 [128][68].
// ===========================================================================
#define A_KW 68
#define A_VW 72
#define A_KBUF (64 * A_KW)
#define A_VBUF (64 * A_VW)
#define A_VOFF (2 * A_KBUF)
#define A_POFF (A_VOFF + 2 * A_VBUF)
#define ATTN_SMEM_BYTES ((A_POFF + 128 * 68) * 4)   // 106496

__global__ void __launch_bounds__(256) attn_tc_kernel(
    const float* __restrict__ qkv, float* __restrict__ attout)
{
    extern __shared__ float asm_[];
    const uint32_t sb = smem_u32(asm_);
    uint32_t* Ps = (uint32_t*)(asm_ + A_POFF);

    const int qt  = blockIdx.x;
    const int h   = blockIdx.y;
    const int b   = blockIdx.z;
    const int tid = threadIdx.x;
    const int w   = tid >> 5;
    const int L   = tid & 31;
    const int gid = L >> 2;
    const int tig = L & 3;
    const int wrow = w * 16;

    const float* qbase = qkv + (size_t)b * SEQ * C3 + h * HD;
    const float* kbase = qbase + C_EMBED;
    const float* vbase = qbase + 2 * C_EMBED;

    // ---- Q fragments in registers (scale folded before rna rounding) ----
    uint32_t qf[8][4];
    {
        const float* qr0 = qbase + (size_t)(qt * 128 + wrow + gid) * C3;
        const float* qr1 = qr0 + 8 * C3;
#pragma unroll
        for (int ks = 0; ks < 8; ks++) {
            const int c = 8 * ks + tig;
            qf[ks][0] = f2tf32(qr0[c] * 0.125f);
            qf[ks][1] = f2tf32(qr1[c] * 0.125f);
            qf[ks][2] = f2tf32(qr0[c + 4] * 0.125f);
            qf[ks][3] = f2tf32(qr1[c + 4] * 0.125f);
        }
    }

    float o[8][4];
#pragma unroll
    for (int nt = 0; nt < 8; nt++)
#pragma unroll
        for (int e = 0; e < 4; e++) o[nt][e] = 0.f;
    float m0 = -1e30f, m1 = -1e30f, l0 = 0.f, l1 = 0.f;

    const int rmax_w = qt * 128 + wrow + 15;
    const int ntiles = 2 * qt + 2;

    // issue K/V tile j into buffer bf (8 cp.async + commit by caller)
    auto issue = [&](int j, int bf) {
#pragma unroll
        for (int u = 0; u < 4; u++) {
            int fid = u * 256 + tid;
            int r   = fid >> 4;
            int c4  = fid & 15;
            const size_t grow = (size_t)(j * 64 + r) * C3 + c4 * 4;
            cp_async16(sb + (uint32_t)((bf * A_KBUF + r * A_KW + c4 * 4) * 4),
                       kbase + grow);
            cp_async16(sb + (uint32_t)((A_VOFF + bf * A_VBUF + r * A_VW + c4 * 4) * 4),
                       vbase + grow);
        }
    };

    issue(0, 0);
    cp_commit();

    for (int j0 = 0; j0 < ntiles; j0++) {
        const int bf = j0 & 1;
        if (j0 + 1 < ntiles) { issue(j0 + 1, bf ^ 1); cp_commit(); cp_wait1(); }
        else                 { cp_wait0(); }
        __syncthreads();

        if (j0 * 64 <= rmax_w) {
            const float* Kf = asm_ + bf * A_KBUF;
            const float* Vf = asm_ + A_VOFF + bf * A_VBUF;

            // ---- S = Q K^T ----
            float s[8][4];
#pragma unroll
            for (int nt = 0; nt < 8; nt++)
#pragma unroll
                for (int e = 0; e < 4; e++) s[nt][e] = 0.f;

#pragma unroll
            for (int ks = 0; ks < 8; ks++) {
#pragma unroll
                for (int nt = 0; nt < 8; nt++) {
                    uint32_t kb[2];
                    const int rk = (nt * 8 + gid) * A_KW + 8 * ks + tig;
                    kb[0] = f2tf32(Kf[rk]);
                    kb[1] = f2tf32(Kf[rk + 4]);
                    mma16n8k8(s[nt], qf[ks], kb);
                }
            }

            // ---- causal mask ----
            const int qr0 = qt * 128 + wrow + gid;
            if (j0 * 64 + 63 > qt * 128 + wrow) {
#pragma unroll
                for (int nt = 0; nt < 8; nt++) {
                    const int c0g = j0 * 64 + nt * 8 + 2 * tig;
                    if (c0g     > qr0)     s[nt][0] = -1e30f;
                    if (c0g + 1 > qr0)     s[nt][1] = -1e30f;
                    if (c0g     > qr0 + 8) s[nt][2] = -1e30f;
                    if (c0g + 1 > qr0 + 8) s[nt][3] = -1e30f;
                }
            }

            // ---- online softmax ----
            float mloc0 = -1e30f, mloc1 = -1e30f;
#pragma unroll
            for (int nt = 0; nt < 8; nt++) {
                mloc0 = fmaxf(mloc0, fmaxf(s[nt][0], s[nt][1]));
                mloc1 = fmaxf(mloc1, fmaxf(s[nt][2], s[nt][3]));
            }
            mloc0 = fmaxf(mloc0, __shfl_xor_sync(0xffffffffu, mloc0, 1));
            mloc0 = fmaxf(mloc0, __shfl_xor_sync(0xffffffffu, mloc0, 2));
            mloc1 = fmaxf(mloc1, __shfl_xor_sync(0xffffffffu, mloc1, 1));
            mloc1 = fmaxf(mloc1, __shfl_xor_sync(0xffffffffu, mloc1, 2));

            const float mn0 = fmaxf(m0, mloc0);
            const float mn1 = fmaxf(m1, mloc1);
            const float cr0 = __expf(m0 - mn0);
            const float cr1 = __expf(m1 - mn1);

            float rs0 = 0.f, rs1 = 0.f;
#pragma unroll
            for (int nt = 0; nt < 8; nt++) {
                s[nt][0] = __expf(s[nt][0] - mn0);
                s[nt][1] = __expf(s[nt][1] - mn0);
                s[nt][2] = __expf(s[nt][2] - mn1);
                s[nt][3] = __expf(s[nt][3] - mn1);
                rs0 += s[nt][0] + s[nt][1];
                rs1 += s[nt][2] + s[nt][3];
            }
            rs0 += __shfl_xor_sync(0xffffffffu, rs0, 1);
            rs0 += __shfl_xor_sync(0xffffffffu, rs0, 2);
            rs1 += __shfl_xor_sync(0xffffffffu, rs1, 1);
            rs1 += __shfl_xor_sync(0xffffffffu, rs1, 2);

            l0 = l0 * cr0 + rs0;
            l1 = l1 * cr1 + rs1;
            m0 = mn0;
            m1 = mn1;
#pragma unroll
            for (int nt = 0; nt < 8; nt++) {
                o[nt][0] *= cr0; o[nt][1] *= cr0;
                o[nt][2] *= cr1; o[nt][3] *= cr1;
            }

            // ---- stage P (warp-private rows) ----
#pragma unroll
            for (int nt = 0; nt < 8; nt++) {
                const int pb = (wrow + gid) * 68 + nt * 8 + 2 * tig;
                Ps[pb]              = f2tf32(s[nt][0]);
                Ps[pb + 1]          = f2tf32(s[nt][1]);
                Ps[pb + 8 * 68]     = f2tf32(s[nt][2]);
                Ps[pb + 8 * 68 + 1] = f2tf32(s[nt][3]);
            }
            __syncwarp();

            // ---- O += P V ----
#pragma unroll
            for (int ks = 0; ks < 8; ks++) {
                uint32_t pa[4];
                const int rp = (wrow + gid) * 68 + 8 * ks + tig;
                pa[0] = Ps[rp];
                pa[1] = Ps[rp + 8 * 68];
                pa[2] = Ps[rp + 4];
                pa[3] = Ps[rp + 8 * 68 + 4];
#pragma unroll
                for (int nt = 0; nt < 8; nt++) {
                    uint32_t vb[2];
                    const int rv = (8 * ks + tig) * A_VW + nt * 8 + gid;
                    vb[0] = f2tf32(Vf[rv]);
                    vb[1] = f2tf32(Vf[rv + 4 * A_VW]);
                    mma16n8k8(o[nt], pa, vb);
                }
            }
            __syncwarp();
        }

        __syncthreads();   // all warps done with buffer bf before overwrite
    }

    // ---- normalize + write ----
    const float inv0 = 1.f / l0;
    const float inv1 = 1.f / l1;
    const int t0 = qt * 128 + wrow + gid;
#pragma unroll
    for (int nt = 0; nt < 8; nt++) {
        const int d = h * HD + nt * 8 + 2 * tig;
        float2 v0 = make_float2(o[nt][0] * inv0, o[nt][1] * inv0);
        *(float2*)&attout[(size_t)(b * SEQ + t0) * C_EMBED + d] = v0;
        float2 v1 = make_float2(o[nt][2] * inv1, o[nt][3] * inv1);
        *(float2*)&attout[(size_t)(b * SEQ + t0 + 8) * C_EMBED + d] = v1;
    }
}

// ---------------------------------------------------------------------------
extern "C" void kernel_launch(void* const* d_in, const int* in_sizes, int n_in,
                              void* d_out, int out_size)
{
    const float* x     = (const float*)d_in[0];
    const float* Wqkv  = (const float*)d_in[1];
    const float* bqkv  = (const float*)d_in[2];
    const float* Wproj = (const float*)d_in[3];
    const float* bproj = (const float*)d_in[4];
    float* out = (float*)d_out;

    float *qkv, *att;
    cudaGetSymbolAddress((void**)&qkv, g_qkv);
    cudaGetSymbolAddress((void**)&att, g_att);

    cudaFuncSetAttribute(gemm_tf32_kernel, cudaFuncAttributeMaxDynamicSharedMemorySize,
                         GEMM_SMEM_BYTES);
    cudaFuncSetAttribute(attn_tc_kernel, cudaFuncAttributeMaxDynamicSharedMemorySize,
                         ATTN_SMEM_BYTES);

    // 1) QKV projection
    dim3 g1(C3 / 128, MROWS / 128);
    gemm_tf32_kernel<<<g1, 256, GEMM_SMEM_BYTES>>>(x, Wqkv, bqkv, qkv, MROWS, C3, C_EMBED);

    // 2) Causal flash attention
    dim3 g2(SEQ / 128, NH, BATCH);
    attn_tc_kernel<<<g2, 256, ATTN_SMEM_BYTES>>>(qkv, att);

    // 3) Output projection
    dim3 g3(C_EMBED / 128, MROWS / 128);
    gemm_tf32_kernel<<<g3, 256, GEMM_SMEM_BYTES>>>(att, Wproj, bproj, out, MROWS, C_EMBED, C_EMBED);
}

// round 7
// speedup vs baseline: 3.5037x; 1.0937x over previous
#include <cuda_runtime.h>
#include <math.h>
#include <stdint.h>

#define C_EMBED 768
#define NH 12
#define HD 64
#define BATCH 2
#define SEQ 4096
#define MROWS (BATCH*SEQ)        // 8192
#define C3 (3*C_EMBED)           // 2304

// Scratch (no allocations allowed) — tf32 bit buffers
__device__ __align__(16) uint32_t g_qkv[(size_t)MROWS * C3];          // 75.5 MB
__device__ __align__(16) uint32_t g_att[(size_t)MROWS * C_EMBED];     // 25 MB
__device__ __align__(16) uint32_t g_xt[(size_t)MROWS * C_EMBED];      // 25 MB
__device__ __align__(16) uint32_t g_wqkvt[(size_t)C_EMBED * C3];      // 7 MB
__device__ __align__(16) uint32_t g_wprojt[(size_t)C_EMBED * C_EMBED];// 2.4 MB

// ---------------------------------------------------------------------------
// helpers
// ---------------------------------------------------------------------------
__device__ __forceinline__ uint32_t f2tf32(float v) {
    uint32_t t;
    asm("cvt.rna.tf32.f32 %0, %1;" : "=r"(t) : "f"(v));
    return t;
}

__device__ __forceinline__ void mma16n8k8(float* d, const uint32_t* a, const uint32_t* b) {
    asm volatile(
        "mma.sync.aligned.m16n8k8.row.col.f32.tf32.tf32.f32 "
        "{%0,%1,%2,%3}, {%4,%5,%6,%7}, {%8,%9}, {%0,%1,%2,%3};"
        : "+f"(d[0]), "+f"(d[1]), "+f"(d[2]), "+f"(d[3])
        : "r"(a[0]), "r"(a[1]), "r"(a[2]), "r"(a[3]), "r"(b[0]), "r"(b[1]));
}

__device__ __forceinline__ uint32_t smem_u32(const void* p) {
    uint32_t a;
    asm("{ .reg .u64 t; cvta.to.shared.u64 t, %1; cvt.u32.u64 %0, t; }"
        : "=r"(a) : "l"(p));
    return a;
}

__device__ __forceinline__ void cp_async16(uint32_t saddr, const void* gptr) {
    asm volatile("cp.async.ca.shared.global [%0], [%1], 16;"
                 :: "r"(saddr), "l"(gptr));
}
__device__ __forceinline__ void cp_commit() {
    asm volatile("cp.async.commit_group;" ::: "memory");
}
__device__ __forceinline__ void cp_wait1() {
    asm volatile("cp.async.wait_group 1;" ::: "memory");
}
__device__ __forceinline__ void cp_wait0() {
    asm volatile("cp.async.wait_group 0;" ::: "memory");
}

// ---------------------------------------------------------------------------
// elementwise fp32 -> tf32-bits pre-pass
// ---------------------------------------------------------------------------
__global__ void __launch_bounds__(256) cvt_tf32_kernel(
    const float4* __restrict__ in, uint4* __restrict__ out, int n4)
{
    int i = blockIdx.x * blockDim.x + threadIdx.x;
    if (i < n4) {
        float4 v = in[i];
        uint4 t;
        t.x = f2tf32(v.x); t.y = f2tf32(v.y);
        t.z = f2tf32(v.z); t.w = f2tf32(v.w);
        out[i] = t;
    }
}

// ===========================================================================
// tf32-bit mma GEMM, cp.async double-buffered: C = A@B + bias
// A, B already tf32 bits. MODE 0: fp32 output. MODE 1: tf32-bit output with
// 1/sqrt(d)=0.125 folded into columns c < C_EMBED (the Q block of QKV).
// ===========================================================================
#define G_AW 36
#define G_BW 136
#define G_ABUF (128 * G_AW)
#define G_BBUF (32 * G_BW)
#define G_BOFF (2 * G_ABUF)
#define GEMM_SMEM_BYTES ((2 * G_ABUF + 2 * G_BBUF) * 4)   // 71680

template<int MODE>
__global__ void __launch_bounds__(256, 2) gemm_tf32_kernel(
    const uint32_t* __restrict__ A, const uint32_t* __restrict__ Bm,
    const float* __restrict__ bias, float* __restrict__ Cm,
    int M, int N, int K)
{
    extern __shared__ uint32_t gsm[];
    const uint32_t sb = smem_u32(gsm);

    const int tid = threadIdx.x;
    const int w   = tid >> 5;
    const int L   = tid & 31;
    const int gid = L >> 2;
    const int tig = L & 3;
    const int row0 = blockIdx.y * 128;
    const int col0 = blockIdx.x * 128;
    const int m0w = (w & 1) * 64;
    const int n0w = (w >> 1) * 32;
    const int nk = K >> 5;

    float acc[4][4][4];
#pragma unroll
    for (int mt = 0; mt < 4; mt++)
#pragma unroll
        for (int nt = 0; nt < 4; nt++)
#pragma unroll
            for (int e = 0; e < 4; e++) acc[mt][nt][e] = 0.f;

    auto issue = [&](int t, int bf) {
        const int kb = t * 32;
#pragma unroll
        for (int u = 0; u < 4; u++) {
            int fid = u * 256 + tid;
            int r   = fid >> 3;
            int c4  = fid & 7;
            cp_async16(sb + (uint32_t)((bf * G_ABUF + r * G_AW + c4 * 4) * 4),
                       &A[(size_t)(row0 + r) * K + kb + c4 * 4]);
        }
#pragma unroll
        for (int u = 0; u < 4; u++) {
            int fid = u * 256 + tid;
            int k   = fid >> 5;
            int n4  = fid & 31;
            cp_async16(sb + (uint32_t)((G_BOFF + bf * G_BBUF + k * G_BW + n4 * 4) * 4),
                       &Bm[(size_t)(kb + k) * N + col0 + n4 * 4]);
        }
    };

    issue(0, 0);
    cp_commit();

    for (int t = 0; t < nk; t++) {
        const int bf = t & 1;
        if (t + 1 < nk) { issue(t + 1, bf ^ 1); cp_commit(); cp_wait1(); }
        else            { cp_wait0(); }
        __syncthreads();

        const uint32_t* Af = gsm + bf * G_ABUF;
        const uint32_t* Bf = gsm + G_BOFF + bf * G_BBUF;

#pragma unroll
        for (int ks = 0; ks < 4; ks++) {
            const int k0 = ks * 8;
            uint32_t af[4][4];
#pragma unroll
            for (int mt = 0; mt < 4; mt++) {
                const int r = m0w + mt * 16 + gid;
                af[mt][0] = Af[r * G_AW + k0 + tig];
                af[mt][1] = Af[(r + 8) * G_AW + k0 + tig];
                af[mt][2] = Af[r * G_AW + k0 + tig + 4];
                af[mt][3] = Af[(r + 8) * G_AW + k0 + tig + 4];
            }
            uint32_t bfr[4][2];
#pragma unroll
            for (int nt = 0; nt < 4; nt++) {
                const int n = n0w + nt * 8 + gid;
                bfr[nt][0] = Bf[(k0 + tig) * G_BW + n];
                bfr[nt][1] = Bf[(k0 + tig + 4) * G_BW + n];
            }
#pragma unroll
            for (int mt = 0; mt < 4; mt++)
#pragma unroll
                for (int nt = 0; nt < 4; nt++)
                    mma16n8k8(acc[mt][nt], af[mt], bfr[nt]);
        }
        __syncthreads();
    }

    // epilogue
#pragma unroll
    for (int mt = 0; mt < 4; mt++) {
        const int r = row0 + m0w + mt * 16 + gid;
#pragma unroll
        for (int nt = 0; nt < 4; nt++) {
            const int c = col0 + n0w + nt * 8 + 2 * tig;
            const float b0 = bias[c], b1 = bias[c + 1];
            if (MODE == 0) {
                float2 v0 = make_float2(acc[mt][nt][0] + b0, acc[mt][nt][1] + b1);
                *(float2*)&Cm[(size_t)r * N + c] = v0;
                float2 v1 = make_float2(acc[mt][nt][2] + b0, acc[mt][nt][3] + b1);
                *(float2*)&Cm[(size_t)(r + 8) * N + c] = v1;
            } else {
                const float sc = (c < C_EMBED) ? 0.125f : 1.0f;   // Q-scale fold
                uint32_t* Co = (uint32_t*)Cm;
                uint2 v0, v1;
                v0.x = f2tf32((acc[mt][nt][0] + b0) * sc);
                v0.y = f2tf32((acc[mt][nt][1] + b1) * sc);
                v1.x = f2tf32((acc[mt][nt][2] + b0) * sc);
                v1.y = f2tf32((acc[mt][nt][3] + b1) * sc);
                *(uint2*)&Co[(size_t)r * N + c] = v0;
                *(uint2*)&Co[(size_t)(r + 8) * N + c] = v1;
            }
        }
    }
}

// ===========================================================================
// tf32-bit mma flash attention (causal), 128-row Q tiles, cp.async K/V.
// qkv buffer holds tf32 bits (Q pre-scaled). Zero cvt in the mma paths.
// ===========================================================================
#define A_KW 68
#define A_VW 72
#define A_KBUF (64 * A_KW)
#define A_VBUF (64 * A_VW)
#define A_VOFF (2 * A_KBUF)
#define A_POFF (A_VOFF + 2 * A_VBUF)
#define ATTN_SMEM_BYTES ((A_POFF + 128 * 68) * 4)   // 106496

__global__ void __launch_bounds__(256) attn_tc_kernel(
    const uint32_t* __restrict__ qkv, uint32_t* __restrict__ attout)
{
    extern __shared__ uint32_t asm_[];
    const uint32_t sb = smem_u32(asm_);
    uint32_t* Ps = asm_ + A_POFF;

    const int qt  = blockIdx.x;
    const int h   = blockIdx.y;
    const int b   = blockIdx.z;
    const int tid = threadIdx.x;
    const int w   = tid >> 5;
    const int L   = tid & 31;
    const int gid = L >> 2;
    const int tig = L & 3;
    const int wrow = w * 16;

    const uint32_t* qbase = qkv + (size_t)b * SEQ * C3 + h * HD;
    const uint32_t* kbase = qbase + C_EMBED;
    const uint32_t* vbase = qbase + 2 * C_EMBED;

    // ---- Q fragments: ready tf32 bits straight from gmem ----
    uint32_t qf[8][4];
    {
        const uint32_t* qr0 = qbase + (size_t)(qt * 128 + wrow + gid) * C3;
        const uint32_t* qr1 = qr0 + 8 * C3;
#pragma unroll
        for (int ks = 0; ks < 8; ks++) {
            const int c = 8 * ks + tig;
            qf[ks][0] = qr0[c];
            qf[ks][1] = qr1[c];
            qf[ks][2] = qr0[c + 4];
            qf[ks][3] = qr1[c + 4];
        }
    }

    float o[8][4];
#pragma unroll
    for (int nt = 0; nt < 8; nt++)
#pragma unroll
        for (int e = 0; e < 4; e++) o[nt][e] = 0.f;
    float m0 = -1e30f, m1 = -1e30f, l0 = 0.f, l1 = 0.f;

    const int rmax_w = qt * 128 + wrow + 15;
    const int ntiles = 2 * qt + 2;

    auto issue = [&](int j, int bf) {
#pragma unroll
        for (int u = 0; u < 4; u++) {
            int fid = u * 256 + tid;
            int r   = fid >> 4;
            int c4  = fid & 15;
            const size_t grow = (size_t)(j * 64 + r) * C3 + c4 * 4;
            cp_async16(sb + (uint32_t)((bf * A_KBUF + r * A_KW + c4 * 4) * 4),
                       kbase + grow);
            cp_async16(sb + (uint32_t)((A_VOFF + bf * A_VBUF + r * A_VW + c4 * 4) * 4),
                       vbase + grow);
        }
    };

    issue(0, 0);
    cp_commit();

    for (int j0 = 0; j0 < ntiles; j0++) {
        const int bf = j0 & 1;
        if (j0 + 1 < ntiles) { issue(j0 + 1, bf ^ 1); cp_commit(); cp_wait1(); }
        else                 { cp_wait0(); }
        __syncthreads();

        if (j0 * 64 <= rmax_w) {
            const uint32_t* Kf = asm_ + bf * A_KBUF;
            const uint32_t* Vf = asm_ + A_VOFF + bf * A_VBUF;

            // ---- S = Q K^T ----
            float s[8][4];
#pragma unroll
            for (int nt = 0; nt < 8; nt++)
#pragma unroll
                for (int e = 0; e < 4; e++) s[nt][e] = 0.f;

#pragma unroll
            for (int ks = 0; ks < 8; ks++) {
#pragma unroll
                for (int nt = 0; nt < 8; nt++) {
                    uint32_t kb[2];
                    const int rk = (nt * 8 + gid) * A_KW + 8 * ks + tig;
                    kb[0] = Kf[rk];
                    kb[1] = Kf[rk + 4];
                    mma16n8k8(s[nt], qf[ks], kb);
                }
            }

            // ---- causal mask ----
            const int qr0 = qt * 128 + wrow + gid;
            if (j0 * 64 + 63 > qt * 128 + wrow) {
#pragma unroll
                for (int nt = 0; nt < 8; nt++) {
                    const int c0g = j0 * 64 + nt * 8 + 2 * tig;
                    if (c0g     > qr0)     s[nt][0] = -1e30f;
                    if (c0g + 1 > qr0)     s[nt][1] = -1e30f;
                    if (c0g     > qr0 + 8) s[nt][2] = -1e30f;
                    if (c0g + 1 > qr0 + 8) s[nt][3] = -1e30f;
                }
            }

            // ---- online softmax ----
            float mloc0 = -1e30f, mloc1 = -1e30f;
#pragma unroll
            for (int nt = 0; nt < 8; nt++) {
                mloc0 = fmaxf(mloc0, fmaxf(s[nt][0], s[nt][1]));
                mloc1 = fmaxf(mloc1, fmaxf(s[nt][2], s[nt][3]));
            }
            mloc0 = fmaxf(mloc0, __shfl_xor_sync(0xffffffffu, mloc0, 1));
            mloc0 = fmaxf(mloc0, __shfl_xor_sync(0xffffffffu, mloc0, 2));
            mloc1 = fmaxf(mloc1, __shfl_xor_sync(0xffffffffu, mloc1, 1));
            mloc1 = fmaxf(mloc1, __shfl_xor_sync(0xffffffffu, mloc1, 2));

            const float mn0 = fmaxf(m0, mloc0);
            const float mn1 = fmaxf(m1, mloc1);
            const float cr0 = __expf(m0 - mn0);
            const float cr1 = __expf(m1 - mn1);

            float rs0 = 0.f, rs1 = 0.f;
#pragma unroll
            for (int nt = 0; nt < 8; nt++) {
                s[nt][0] = __expf(s[nt][0] - mn0);
                s[nt][1] = __expf(s[nt][1] - mn0);
                s[nt][2] = __expf(s[nt][2] - mn1);
                s[nt][3] = __expf(s[nt][3] - mn1);
                rs0 += s[nt][0] + s[nt][1];
                rs1 += s[nt][2] + s[nt][3];
            }
            rs0 += __shfl_xor_sync(0xffffffffu, rs0, 1);
            rs0 += __shfl_xor_sync(0xffffffffu, rs0, 2);
            rs1 += __shfl_xor_sync(0xffffffffu, rs1, 1);
            rs1 += __shfl_xor_sync(0xffffffffu, rs1, 2);

            l0 = l0 * cr0 + rs0;
            l1 = l1 * cr1 + rs1;
            m0 = mn0;
            m1 = mn1;
#pragma unroll
            for (int nt = 0; nt < 8; nt++) {
                o[nt][0] *= cr0; o[nt][1] *= cr0;
                o[nt][2] *= cr1; o[nt][3] *= cr1;
            }

            // ---- stage P (warp-private rows) ----
#pragma unroll
            for (int nt = 0; nt < 8; nt++) {
                const int pb = (wrow + gid) * 68 + nt * 8 + 2 * tig;
                Ps[pb]              = f2tf32(s[nt][0]);
                Ps[pb + 1]          = f2tf32(s[nt][1]);
                Ps[pb + 8 * 68]     = f2tf32(s[nt][2]);
                Ps[pb + 8 * 68 + 1] = f2tf32(s[nt][3]);
            }
            __syncwarp();

            // ---- O += P V ----
#pragma unroll
            for (int ks = 0; ks < 8; ks++) {
                uint32_t pa[4];
                const int rp = (wrow + gid) * 68 + 8 * ks + tig;
                pa[0] = Ps[rp];
                pa[1] = Ps[rp + 8 * 68];
                pa[2] = Ps[rp + 4];
                pa[3] = Ps[rp + 8 * 68 + 4];
#pragma unroll
                for (int nt = 0; nt < 8; nt++) {
                    uint32_t vb[2];
                    const int rv = (8 * ks + tig) * A_VW + nt * 8 + gid;
                    vb[0] = Vf[rv];
                    vb[1] = Vf[rv + 4 * A_VW];
                    mma16n8k8(o[nt], pa, vb);
                }
            }
            __syncwarp();
        }

        __syncthreads();
    }

    // ---- normalize + write tf32 bits ----
    const float inv0 = 1.f / l0;
    const float inv1 = 1.f / l1;
    const int t0 = qt * 128 + wrow + gid;
#pragma unroll
    for (int nt = 0; nt < 8; nt++) {
        const int d = h * HD + nt * 8 + 2 * tig;
        uint2 v0, v1;
        v0.x = f2tf32(o[nt][0] * inv0);
        v0.y = f2tf32(o[nt][1] * inv0);
        v1.x = f2tf32(o[nt][2] * inv1);
        v1.y = f2tf32(o[nt][3] * inv1);
        *(uint2*)&attout[(size_t)(b * SEQ + t0) * C_EMBED + d] = v0;
        *(uint2*)&attout[(size_t)(b * SEQ + t0 + 8) * C_EMBED + d] = v1;
    }
}

// ---------------------------------------------------------------------------
extern "C" void kernel_launch(void* const* d_in, const int* in_sizes, int n_in,
                              void* d_out, int out_size)
{
    const float* x     = (const float*)d_in[0];
    const float* Wqkv  = (const float*)d_in[1];
    const float* bqkv  = (const float*)d_in[2];
    const float* Wproj = (const float*)d_in[3];
    const float* bproj = (const float*)d_in[4];
    float* out = (float*)d_out;

    uint32_t *qkv, *att, *xt, *wqkvt, *wprojt;
    cudaGetSymbolAddress((void**)&qkv, g_qkv);
    cudaGetSymbolAddress((void**)&att, g_att);
    cudaGetSymbolAddress((void**)&xt, g_xt);
    cudaGetSymbolAddress((void**)&wqkvt, g_wqkvt);
    cudaGetSymbolAddress((void**)&wprojt, g_wprojt);

    cudaFuncSetAttribute(gemm_tf32_kernel<0>, cudaFuncAttributeMaxDynamicSharedMemorySize,
                         GEMM_SMEM_BYTES);
    cudaFuncSetAttribute(gemm_tf32_kernel<1>, cudaFuncAttributeMaxDynamicSharedMemorySize,
                         GEMM_SMEM_BYTES);
    cudaFuncSetAttribute(attn_tc_kernel, cudaFuncAttributeMaxDynamicSharedMemorySize,
                         ATTN_SMEM_BYTES);

    // 0) pre-round inputs/weights to tf32 bits
    {
        int n4x = (MROWS * C_EMBED) / 4;
        cvt_tf32_kernel<<<(n4x + 255) / 256, 256>>>((const float4*)x, (uint4*)xt, n4x);
        int n4w = (C_EMBED * C3) / 4;
        cvt_tf32_kernel<<<(n4w + 255) / 256, 256>>>((const float4*)Wqkv, (uint4*)wqkvt, n4w);
        int n4p = (C_EMBED * C_EMBED) / 4;
        cvt_tf32_kernel<<<(n4p + 255) / 256, 256>>>((const float4*)Wproj, (uint4*)wprojt, n4p);
    }

    // 1) QKV projection -> tf32 bits, Q-scale folded
    dim3 g1(C3 / 128, MROWS / 128);
    gemm_tf32_kernel<1><<<g1, 256, GEMM_SMEM_BYTES>>>(xt, wqkvt, bqkv, (float*)qkv,
                                                      MROWS, C3, C_EMBED);

    // 2) Causal flash attention -> tf32 bits
    dim3 g2(SEQ / 128, NH, BATCH);
    attn_tc_kernel<<<g2, 256, ATTN_SMEM_BYTES>>>(qkv, att);

    // 3) Output projection -> fp32
    dim3 g3(C_EMBED / 128, MROWS / 128);
    gemm_tf32_kernel<0><<<g3, 256, GEMM_SMEM_BYTES>>>(att, wprojt, bproj, out,
                                                      MROWS, C_EMBED, C_EMBED);
}

// round 8
// speedup vs baseline: 3.5533x; 1.0141x over previous
#include <cuda_runtime.h>
#include <math.h>
#include <stdint.h>

#define C_EMBED 768
#define NH 12
#define HD 64
#define BATCH 2
#define SEQ 4096
#define MROWS (BATCH*SEQ)        // 8192
#define C3 (3*C_EMBED)           // 2304

// Scratch (no allocations allowed) — tf32 bit buffers
__device__ __align__(16) uint32_t g_qkv[(size_t)MROWS * C3];          // 75.5 MB
__device__ __align__(16) uint32_t g_att[(size_t)MROWS * C_EMBED];     // 25 MB
__device__ __align__(16) uint32_t g_xt[(size_t)MROWS * C_EMBED];      // 25 MB
__device__ __align__(16) uint32_t g_wqkvt[(size_t)C_EMBED * C3];      // 7 MB
__device__ __align__(16) uint32_t g_wprojt[(size_t)C_EMBED * C_EMBED];// 2.4 MB

// ---------------------------------------------------------------------------
// helpers
// ---------------------------------------------------------------------------
__device__ __forceinline__ uint32_t f2tf32(float v) {
    uint32_t t;
    asm("cvt.rna.tf32.f32 %0, %1;" : "=r"(t) : "f"(v));
    return t;
}

__device__ __forceinline__ void mma16n8k8(float* d, const uint32_t* a, const uint32_t* b) {
    asm volatile(
        "mma.sync.aligned.m16n8k8.row.col.f32.tf32.tf32.f32 "
        "{%0,%1,%2,%3}, {%4,%5,%6,%7}, {%8,%9}, {%0,%1,%2,%3};"
        : "+f"(d[0]), "+f"(d[1]), "+f"(d[2]), "+f"(d[3])
        : "r"(a[0]), "r"(a[1]), "r"(a[2]), "r"(a[3]), "r"(b[0]), "r"(b[1]));
}

__device__ __forceinline__ uint32_t smem_u32(const void* p) {
    uint32_t a;
    asm("{ .reg .u64 t; cvta.to.shared.u64 t, %1; cvt.u32.u64 %0, t; }"
        : "=r"(a) : "l"(p));
    return a;
}

__device__ __forceinline__ void cp_async16(uint32_t saddr, const void* gptr) {
    asm volatile("cp.async.ca.shared.global [%0], [%1], 16;"
                 :: "r"(saddr), "l"(gptr));
}
__device__ __forceinline__ void cp_commit() {
    asm volatile("cp.async.commit_group;" ::: "memory");
}
__device__ __forceinline__ void cp_wait1() {
    asm volatile("cp.async.wait_group 1;" ::: "memory");
}
__device__ __forceinline__ void cp_wait0() {
    asm volatile("cp.async.wait_group 0;" ::: "memory");
}

// ---------------------------------------------------------------------------
// elementwise fp32 -> tf32-bits pre-pass
// ---------------------------------------------------------------------------
__global__ void __launch_bounds__(256) cvt_tf32_kernel(
    const float4* __restrict__ in, uint4* __restrict__ out, int n4)
{
    int i = blockIdx.x * blockDim.x + threadIdx.x;
    if (i < n4) {
        float4 v = in[i];
        uint4 t;
        t.x = f2tf32(v.x); t.y = f2tf32(v.y);
        t.z = f2tf32(v.z); t.w = f2tf32(v.w);
        out[i] = t;
    }
}

// ===========================================================================
// tf32-bit mma GEMM, 3-stage cp.async pipeline, ONE barrier per iteration.
// C = A@B + bias. MODE 0: fp32 out. MODE 1: tf32-bit out, Q-scale folded.
// ===========================================================================
#define G_AW 36
#define G_BW 136
#define G_ABUF (128 * G_AW)               // 4608 words
#define G_BBUF (32 * G_BW)                // 4352 words
#define G_STG (G_ABUF + G_BBUF)           // 8960 words / stage
#define GEMM_SMEM_BYTES (3 * G_STG * 4)   // 107520

template<int MODE>
__global__ void __launch_bounds__(256, 2) gemm_tf32_kernel(
    const uint32_t* __restrict__ A, const uint32_t* __restrict__ Bm,
    const float* __restrict__ bias, float* __restrict__ Cm,
    int M, int N, int K)
{
    extern __shared__ uint32_t gsm[];
    const uint32_t sb = smem_u32(gsm);

    const int tid = threadIdx.x;
    const int w   = tid >> 5;
    const int L   = tid & 31;
    const int gid = L >> 2;
    const int tig = L & 3;
    const int row0 = blockIdx.y * 128;
    const int col0 = blockIdx.x * 128;
    const int m0w = (w & 1) * 64;
    const int n0w = (w >> 1) * 32;
    const int nk = K >> 5;

    float acc[4][4][4];
#pragma unroll
    for (int mt = 0; mt < 4; mt++)
#pragma unroll
        for (int nt = 0; nt < 4; nt++)
#pragma unroll
            for (int e = 0; e < 4; e++) acc[mt][nt][e] = 0.f;

    auto issue = [&](int t, int s) {
        const int kb = t * 32;
        const uint32_t base = sb + (uint32_t)(s * G_STG * 4);
#pragma unroll
        for (int u = 0; u < 4; u++) {
            int fid = u * 256 + tid;
            int r   = fid >> 3;
            int c4  = fid & 7;
            cp_async16(base + (uint32_t)((r * G_AW + c4 * 4) * 4),
                       &A[(size_t)(row0 + r) * K + kb + c4 * 4]);
        }
#pragma unroll
        for (int u = 0; u < 4; u++) {
            int fid = u * 256 + tid;
            int k   = fid >> 5;
            int n4  = fid & 31;
            cp_async16(base + (uint32_t)((G_ABUF + k * G_BW + n4 * 4) * 4),
                       &Bm[(size_t)(kb + k) * N + col0 + n4 * 4]);
        }
    };

    issue(0, 0); cp_commit();
    issue(1, 1); cp_commit();

    for (int t = 0; t < nk; t++) {
        if (t + 1 < nk) cp_wait1(); else cp_wait0();
        __syncthreads();
        if (t + 2 < nk) { issue(t + 2, (t + 2) % 3); cp_commit(); }

        const uint32_t* Af = gsm + (t % 3) * G_STG;
        const uint32_t* Bf = Af + G_ABUF;

#pragma unroll
        for (int ks = 0; ks < 4; ks++) {
            const int k0 = ks * 8;
            uint32_t af[4][4];
#pragma unroll
            for (int mt = 0; mt < 4; mt++) {
                const int r = m0w + mt * 16 + gid;
                af[mt][0] = Af[r * G_AW + k0 + tig];
                af[mt][1] = Af[(r + 8) * G_AW + k0 + tig];
                af[mt][2] = Af[r * G_AW + k0 + tig + 4];
                af[mt][3] = Af[(r + 8) * G_AW + k0 + tig + 4];
            }
            uint32_t bfr[4][2];
#pragma unroll
            for (int nt = 0; nt < 4; nt++) {
                const int n = n0w + nt * 8 + gid;
                bfr[nt][0] = Bf[(k0 + tig) * G_BW + n];
                bfr[nt][1] = Bf[(k0 + tig + 4) * G_BW + n];
            }
#pragma unroll
            for (int mt = 0; mt < 4; mt++)
#pragma unroll
                for (int nt = 0; nt < 4; nt++)
                    mma16n8k8(acc[mt][nt], af[mt], bfr[nt]);
        }
    }

    // epilogue
#pragma unroll
    for (int mt = 0; mt < 4; mt++) {
        const int r = row0 + m0w + mt * 16 + gid;
#pragma unroll
        for (int nt = 0; nt < 4; nt++) {
            const int c = col0 + n0w + nt * 8 + 2 * tig;
            const float b0 = bias[c], b1 = bias[c + 1];
            if (MODE == 0) {
                float2 v0 = make_float2(acc[mt][nt][0] + b0, acc[mt][nt][1] + b1);
                *(float2*)&Cm[(size_t)r * N + c] = v0;
                float2 v1 = make_float2(acc[mt][nt][2] + b0, acc[mt][nt][3] + b1);
                *(float2*)&Cm[(size_t)(r + 8) * N + c] = v1;
            } else {
                const float sc = (c < C_EMBED) ? 0.125f : 1.0f;   // Q-scale fold
                uint32_t* Co = (uint32_t*)Cm;
                uint2 v0, v1;
                v0.x = f2tf32((acc[mt][nt][0] + b0) * sc);
                v0.y = f2tf32((acc[mt][nt][1] + b1) * sc);
                v1.x = f2tf32((acc[mt][nt][2] + b0) * sc);
                v1.y = f2tf32((acc[mt][nt][3] + b1) * sc);
                *(uint2*)&Co[(size_t)r * N + c] = v0;
                *(uint2*)&Co[(size_t)(r + 8) * N + c] = v1;
            }
        }
    }
}

// ===========================================================================
// tf32-bit mma flash attention (causal), 128-row Q tiles, cp.async K/V,
// single barrier per key tile, largest-qt-first scheduling.
// ===========================================================================
#define A_KW 68
#define A_VW 72
#define A_KBUF (64 * A_KW)
#define A_VBUF (64 * A_VW)
#define A_VOFF (2 * A_KBUF)
#define A_POFF (A_VOFF + 2 * A_VBUF)
#define ATTN_SMEM_BYTES ((A_POFF + 128 * 68) * 4)   // 106496

__global__ void __launch_bounds__(256) attn_tc_kernel(
    const uint32_t* __restrict__ qkv, uint32_t* __restrict__ attout)
{
    extern __shared__ uint32_t asm_[];
    const uint32_t sb = smem_u32(asm_);
    uint32_t* Ps = asm_ + A_POFF;

    const int qt  = (int)gridDim.x - 1 - (int)blockIdx.x;   // largest-first
    const int h   = blockIdx.y;
    const int b   = blockIdx.z;
    const int tid = threadIdx.x;
    const int w   = tid >> 5;
    const int L   = tid & 31;
    const int gid = L >> 2;
    const int tig = L & 3;
    const int wrow = w * 16;

    const uint32_t* qbase = qkv + (size_t)b * SEQ * C3 + h * HD;
    const uint32_t* kbase = qbase + C_EMBED;
    const uint32_t* vbase = qbase + 2 * C_EMBED;

    // ---- Q fragments: ready tf32 bits straight from gmem ----
    uint32_t qf[8][4];
    {
        const uint32_t* qr0 = qbase + (size_t)(qt * 128 + wrow + gid) * C3;
        const uint32_t* qr1 = qr0 + 8 * C3;
#pragma unroll
        for (int ks = 0; ks < 8; ks++) {
            const int c = 8 * ks + tig;
            qf[ks][0] = qr0[c];
            qf[ks][1] = qr1[c];
            qf[ks][2] = qr0[c + 4];
            qf[ks][3] = qr1[c + 4];
        }
    }

    float o[8][4];
#pragma unroll
    for (int nt = 0; nt < 8; nt++)
#pragma unroll
        for (int e = 0; e < 4; e++) o[nt][e] = 0.f;
    float m0 = -1e30f, m1 = -1e30f, l0 = 0.f, l1 = 0.f;

    const int rmax_w = qt * 128 + wrow + 15;
    const int ntiles = 2 * qt + 2;

    auto issue = [&](int j, int bf) {
#pragma unroll
        for (int u = 0; u < 4; u++) {
            int fid = u * 256 + tid;
            int r   = fid >> 4;
            int c4  = fid & 15;
            const size_t grow = (size_t)(j * 64 + r) * C3 + c4 * 4;
            cp_async16(sb + (uint32_t)((bf * A_KBUF + r * A_KW + c4 * 4) * 4),
                       kbase + grow);
            cp_async16(sb + (uint32_t)((A_VOFF + bf * A_VBUF + r * A_VW + c4 * 4) * 4),
                       vbase + grow);
        }
    };

    issue(0, 0);
    cp_commit();

    for (int j0 = 0; j0 < ntiles; j0++) {
        cp_wait0();
        __syncthreads();
        if (j0 + 1 < ntiles) { issue(j0 + 1, (j0 + 1) & 1); cp_commit(); }

        if (j0 * 64 <= rmax_w) {
            const int bf = j0 & 1;
            const uint32_t* Kf = asm_ + bf * A_KBUF;
            const uint32_t* Vf = asm_ + A_VOFF + bf * A_VBUF;

            // ---- S = Q K^T ----
            float s[8][4];
#pragma unroll
            for (int nt = 0; nt < 8; nt++)
#pragma unroll
                for (int e = 0; e < 4; e++) s[nt][e] = 0.f;

#pragma unroll
            for (int ks = 0; ks < 8; ks++) {
#pragma unroll
                for (int nt = 0; nt < 8; nt++) {
                    uint32_t kb[2];
                    const int rk = (nt * 8 + gid) * A_KW + 8 * ks + tig;
                    kb[0] = Kf[rk];
                    kb[1] = Kf[rk + 4];
                    mma16n8k8(s[nt], qf[ks], kb);
                }
            }

            // ---- causal mask ----
            const int qr0 = qt * 128 + wrow + gid;
            if (j0 * 64 + 63 > qt * 128 + wrow) {
#pragma unroll
                for (int nt = 0; nt < 8; nt++) {
                    const int c0g = j0 * 64 + nt * 8 + 2 * tig;
                    if (c0g     > qr0)     s[nt][0] = -1e30f;
                    if (c0g + 1 > qr0)     s[nt][1] = -1e30f;
                    if (c0g     > qr0 + 8) s[nt][2] = -1e30f;
                    if (c0g + 1 > qr0 + 8) s[nt][3] = -1e30f;
                }
            }

            // ---- online softmax ----
            float mloc0 = -1e30f, mloc1 = -1e30f;
#pragma unroll
            for (int nt = 0; nt < 8; nt++) {
                mloc0 = fmaxf(mloc0, fmaxf(s[nt][0], s[nt][1]));
                mloc1 = fmaxf(mloc1, fmaxf(s[nt][2], s[nt][3]));
            }
            mloc0 = fmaxf(mloc0, __shfl_xor_sync(0xffffffffu, mloc0, 1));
            mloc0 = fmaxf(mloc0, __shfl_xor_sync(0xffffffffu, mloc0, 2));
            mloc1 = fmaxf(mloc1, __shfl_xor_sync(0xffffffffu, mloc1, 1));
            mloc1 = fmaxf(mloc1, __shfl_xor_sync(0xffffffffu, mloc1, 2));

            const float mn0 = fmaxf(m0, mloc0);
            const float mn1 = fmaxf(m1, mloc1);
            const float cr0 = __expf(m0 - mn0);
            const float cr1 = __expf(m1 - mn1);

            float rs0 = 0.f, rs1 = 0.f;
#pragma unroll
            for (int nt = 0; nt < 8; nt++) {
                s[nt][0] = __expf(s[nt][0] - mn0);
                s[nt][1] = __expf(s[nt][1] - mn0);
                s[nt][2] = __expf(s[nt][2] - mn1);
                s[nt][3] = __expf(s[nt][3] - mn1);
                rs0 += s[nt][0] + s[nt][1];
                rs1 += s[nt][2] + s[nt][3];
            }
            rs0 += __shfl_xor_sync(0xffffffffu, rs0, 1);
            rs0 += __shfl_xor_sync(0xffffffffu, rs0, 2);
            rs1 += __shfl_xor_sync(0xffffffffu, rs1, 1);
            rs1 += __shfl_xor_sync(0xffffffffu, rs1, 2);

            l0 = l0 * cr0 + rs0;
            l1 = l1 * cr1 + rs1;
            m0 = mn0;
            m1 = mn1;
#pragma unroll
            for (int nt = 0; nt < 8; nt++) {
                o[nt][0] *= cr0; o[nt][1] *= cr0;
                o[nt][2] *= cr1; o[nt][3] *= cr1;
            }

            // ---- stage P (warp-private rows) ----
#pragma unroll
            for (int nt = 0; nt < 8; nt++) {
                const int pb = (wrow + gid) * 68 + nt * 8 + 2 * tig;
                Ps[pb]              = f2tf32(s[nt][0]);
                Ps[pb + 1]          = f2tf32(s[nt][1]);
                Ps[pb + 8 * 68]     = f2tf32(s[nt][2]);
                Ps[pb + 8 * 68 + 1] = f2tf32(s[nt][3]);
            }
            __syncwarp();

            // ---- O += P V ----
#pragma unroll
            for (int ks = 0; ks < 8; ks++) {
                uint32_t pa[4];
                const int rp = (wrow + gid) * 68 + 8 * ks + tig;
                pa[0] = Ps[rp];
                pa[1] = Ps[rp + 8 * 68];
                pa[2] = Ps[rp + 4];
                pa[3] = Ps[rp + 8 * 68 + 4];
#pragma unroll
                for (int nt = 0; nt < 8; nt++) {
                    uint32_t vb[2];
                    const int rv = (8 * ks + tig) * A_VW + nt * 8 + gid;
                    vb[0] = Vf[rv];
                    vb[1] = Vf[rv + 4 * A_VW];
                    mma16n8k8(o[nt], pa, vb);
                }
            }
            __syncwarp();
        }
    }

    // ---- normalize + write tf32 bits ----
    const float inv0 = 1.f / l0;
    const float inv1 = 1.f / l1;
    const int t0 = qt * 128 + wrow + gid;
#pragma unroll
    for (int nt = 0; nt < 8; nt++) {
        const int d = h * HD + nt * 8 + 2 * tig;
        uint2 v0, v1;
        v0.x = f2tf32(o[nt][0] * inv0);
        v0.y = f2tf32(o[nt][1] * inv0);
        v1.x = f2tf32(o[nt][2] * inv1);
        v1.y = f2tf32(o[nt][3] * inv1);
        *(uint2*)&attout[(size_t)(b * SEQ + t0) * C_EMBED + d] = v0;
        *(uint2*)&attout[(size_t)(b * SEQ + t0 + 8) * C_EMBED + d] = v1;
    }
}

// ---------------------------------------------------------------------------
extern "C" void kernel_launch(void* const* d_in, const int* in_sizes, int n_in,
                              void* d_out, int out_size)
{
    const float* x     = (const float*)d_in[0];
    const float* Wqkv  = (const float*)d_in[1];
    const float* bqkv  = (const float*)d_in[2];
    const float* Wproj = (const float*)d_in[3];
    const float* bproj = (const float*)d_in[4];
    float* out = (float*)d_out;

    uint32_t *qkv, *att, *xt, *wqkvt, *wprojt;
    cudaGetSymbolAddress((void**)&qkv, g_qkv);
    cudaGetSymbolAddress((void**)&att, g_att);
    cudaGetSymbolAddress((void**)&xt, g_xt);
    cudaGetSymbolAddress((void**)&wqkvt, g_wqkvt);
    cudaGetSymbolAddress((void**)&wprojt, g_wprojt);

    cudaFuncSetAttribute(gemm_tf32_kernel<0>, cudaFuncAttributeMaxDynamicSharedMemorySize,
                         GEMM_SMEM_BYTES);
    cudaFuncSetAttribute(gemm_tf32_kernel<1>, cudaFuncAttributeMaxDynamicSharedMemorySize,
                         GEMM_SMEM_BYTES);
    cudaFuncSetAttribute(attn_tc_kernel, cudaFuncAttributeMaxDynamicSharedMemorySize,
                         ATTN_SMEM_BYTES);

    // 0) pre-round inputs/weights to tf32 bits
    {
        int n4x = (MROWS * C_EMBED) / 4;
        cvt_tf32_kernel<<<(n4x + 255) / 256, 256>>>((const float4*)x, (uint4*)xt, n4x);
        int n4w = (C_EMBED * C3) / 4;
        cvt_tf32_kernel<<<(n4w + 255) / 256, 256>>>((const float4*)Wqkv, (uint4*)wqkvt, n4w);
        int n4p = (C_EMBED * C_EMBED) / 4;
        cvt_tf32_kernel<<<(n4p + 255) / 256, 256>>>((const float4*)Wproj, (uint4*)wprojt, n4p);
    }

    // 1) QKV projection -> tf32 bits, Q-scale folded
    dim3 g1(C3 / 128, MROWS / 128);
    gemm_tf32_kernel<1><<<g1, 256, GEMM_SMEM_BYTES>>>(xt, wqkvt, bqkv, (float*)qkv,
                                                      MROWS, C3, C_EMBED);

    // 2) Causal flash attention -> tf32 bits
    dim3 g2(SEQ / 128, NH, BATCH);
    attn_tc_kernel<<<g2, 256, ATTN_SMEM_BYTES>>>(qkv, att);

    // 3) Output projection -> fp32
    dim3 g3(C_EMBED / 128, MROWS / 128);
    gemm_tf32_kernel<0><<<g3, 256, GEMM_SMEM_BYTES>>>(att, wprojt, bproj, out,
                                                      MROWS, C_EMBED, C_EMBED);
}

// round 9
// speedup vs baseline: 3.6665x; 1.0319x over previous
#include <cuda_runtime.h>
#include <math.h>
#include <stdint.h>

#define C_EMBED 768
#define NH 12
#define HD 64
#define BATCH 2
#define SEQ 4096
#define MROWS (BATCH*SEQ)        // 8192
#define C3 (3*C_EMBED)           // 2304

// Scratch (no allocations allowed) — tf32 bit buffers
__device__ __align__(16) uint32_t g_qkv[(size_t)MROWS * C3];          // 75.5 MB
__device__ __align__(16) uint32_t g_att[(size_t)MROWS * C_EMBED];     // 25 MB
__device__ __align__(16) uint32_t g_xt[(size_t)MROWS * C_EMBED];      // 25 MB
__device__ __align__(16) uint32_t g_wqkvt[(size_t)C_EMBED * C3];      // 7 MB
__device__ __align__(16) uint32_t g_wprojt[(size_t)C_EMBED * C_EMBED];// 2.4 MB

// ---------------------------------------------------------------------------
// helpers
// ---------------------------------------------------------------------------
__device__ __forceinline__ uint32_t f2tf32(float v) {
    uint32_t t;
    asm("cvt.rna.tf32.f32 %0, %1;" : "=r"(t) : "f"(v));
    return t;
}

__device__ __forceinline__ void mma16n8k8(float* d, const uint32_t* a, const uint32_t* b) {
    asm volatile(
        "mma.sync.aligned.m16n8k8.row.col.f32.tf32.tf32.f32 "
        "{%0,%1,%2,%3}, {%4,%5,%6,%7}, {%8,%9}, {%0,%1,%2,%3};"
        : "+f"(d[0]), "+f"(d[1]), "+f"(d[2]), "+f"(d[3])
        : "r"(a[0]), "r"(a[1]), "r"(a[2]), "r"(a[3]), "r"(b[0]), "r"(b[1]));
}

// one instruction -> 4 fragment registers (8x4 tf32 blocks)
__device__ __forceinline__ void ldmx4(uint32_t* r, uint32_t a) {
    asm volatile("ldmatrix.sync.aligned.m8n8.x4.shared.b16 {%0,%1,%2,%3}, [%4];"
                 : "=r"(r[0]), "=r"(r[1]), "=r"(r[2]), "=r"(r[3]) : "r"(a));
}

__device__ __forceinline__ uint32_t smem_u32(const void* p) {
    uint32_t a;
    asm("{ .reg .u64 t; cvta.to.shared.u64 t, %1; cvt.u32.u64 %0, t; }"
        : "=r"(a) : "l"(p));
    return a;
}

__device__ __forceinline__ void cp_async16(uint32_t saddr, const void* gptr) {
    asm volatile("cp.async.ca.shared.global [%0], [%1], 16;"
                 :: "r"(saddr), "l"(gptr));
}
__device__ __forceinline__ void cp_commit() {
    asm volatile("cp.async.commit_group;" ::: "memory");
}
__device__ __forceinline__ void cp_wait1() {
    asm volatile("cp.async.wait_group 1;" ::: "memory");
}
__device__ __forceinline__ void cp_wait0() {
    asm volatile("cp.async.wait_group 0;" ::: "memory");
}

// ---------------------------------------------------------------------------
// elementwise fp32 -> tf32-bits pre-pass
// ---------------------------------------------------------------------------
__global__ void __launch_bounds__(256) cvt_tf32_kernel(
    const float4* __restrict__ in, uint4* __restrict__ out, int n4)
{
    int i = blockIdx.x * blockDim.x + threadIdx.x;
    if (i < n4) {
        float4 v = in[i];
        uint4 t;
        t.x = f2tf32(v.x); t.y = f2tf32(v.y);
        t.z = f2tf32(v.z); t.w = f2tf32(v.w);
        out[i] = t;
    }
}

// ===========================================================================
// tf32-bit mma GEMM, 2-stage cp.async (verified R7 structure) + A via
// ldmatrix. C = A@B + bias. MODE 0: fp32 out. MODE 1: tf32-bit out, Q-scaled.
// ===========================================================================
#define G_AW 36
#define G_BW 136
#define G_ABUF (128 * G_AW)
#define G_BBUF (32 * G_BW)
#define G_BOFF (2 * G_ABUF)
#define GEMM_SMEM_BYTES ((2 * G_ABUF + 2 * G_BBUF) * 4)   // 71680

template<int MODE>
__global__ void __launch_bounds__(256, 2) gemm_tf32_kernel(
    const uint32_t* __restrict__ A, const uint32_t* __restrict__ Bm,
    const float* __restrict__ bias, float* __restrict__ Cm,
    int M, int N, int K)
{
    extern __shared__ uint32_t gsm[];
    const uint32_t sb = smem_u32(gsm);

    const int tid = threadIdx.x;
    const int w   = tid >> 5;
    const int L   = tid & 31;
    const int gid = L >> 2;
    const int tig = L & 3;
    const int row0 = blockIdx.y * 128;
    const int col0 = blockIdx.x * 128;
    const int m0w = (w & 1) * 64;
    const int n0w = (w >> 1) * 32;
    const int nk = K >> 5;

    // ldmatrix lane mapping for A fragments:
    // mat0 rows+0 k+0 | mat1 rows+8 k+0 | mat2 rows+0 k+4 | mat3 rows+8 k+4
    const int am = L >> 3;
    const int arow_off = ((am & 1) << 3) + (L & 7);
    const int acol_off = (am >> 1) << 2;

    float acc[4][4][4];
#pragma unroll
    for (int mt = 0; mt < 4; mt++)
#pragma unroll
        for (int nt = 0; nt < 4; nt++)
#pragma unroll
            for (int e = 0; e < 4; e++) acc[mt][nt][e] = 0.f;

    auto issue = [&](int t, int bf) {
        const int kb = t * 32;
#pragma unroll
        for (int u = 0; u < 4; u++) {
            int fid = u * 256 + tid;
            int r   = fid >> 3;
            int c4  = fid & 7;
            cp_async16(sb + (uint32_t)((bf * G_ABUF + r * G_AW + c4 * 4) * 4),
                       &A[(size_t)(row0 + r) * K + kb + c4 * 4]);
        }
#pragma unroll
        for (int u = 0; u < 4; u++) {
            int fid = u * 256 + tid;
            int k   = fid >> 5;
            int n4  = fid & 31;
            cp_async16(sb + (uint32_t)((G_BOFF + bf * G_BBUF + k * G_BW + n4 * 4) * 4),
                       &Bm[(size_t)(kb + k) * N + col0 + n4 * 4]);
        }
    };

    issue(0, 0);
    cp_commit();

    for (int t = 0; t < nk; t++) {
        const int bf = t & 1;
        if (t + 1 < nk) { issue(t + 1, bf ^ 1); cp_commit(); cp_wait1(); }
        else            { cp_wait0(); }
        __syncthreads();

        const uint32_t sbA = sb + (uint32_t)(bf * G_ABUF * 4);
        const uint32_t* Bf = gsm + G_BOFF + bf * G_BBUF;

#pragma unroll
        for (int ks = 0; ks < 4; ks++) {
            const int k0 = ks * 8;
            uint32_t af[4][4];
#pragma unroll
            for (int mt = 0; mt < 4; mt++) {
                ldmx4(af[mt], sbA + (uint32_t)(((m0w + mt * 16 + arow_off) * G_AW
                                                + k0 + acol_off) * 4));
            }
            uint32_t bfr[4][2];
#pragma unroll
            for (int nt = 0; nt < 4; nt++) {
                const int n = n0w + nt * 8 + gid;
                bfr[nt][0] = Bf[(k0 + tig) * G_BW + n];
                bfr[nt][1] = Bf[(k0 + tig + 4) * G_BW + n];
            }
#pragma unroll
            for (int mt = 0; mt < 4; mt++)
#pragma unroll
                for (int nt = 0; nt < 4; nt++)
                    mma16n8k8(acc[mt][nt], af[mt], bfr[nt]);
        }
        __syncthreads();
    }

    // epilogue
#pragma unroll
    for (int mt = 0; mt < 4; mt++) {
        const int r = row0 + m0w + mt * 16 + gid;
#pragma unroll
        for (int nt = 0; nt < 4; nt++) {
            const int c = col0 + n0w + nt * 8 + 2 * tig;
            const float b0 = bias[c], b1 = bias[c + 1];
            if (MODE == 0) {
                float2 v0 = make_float2(acc[mt][nt][0] + b0, acc[mt][nt][1] + b1);
                *(float2*)&Cm[(size_t)r * N + c] = v0;
                float2 v1 = make_float2(acc[mt][nt][2] + b0, acc[mt][nt][3] + b1);
                *(float2*)&Cm[(size_t)(r + 8) * N + c] = v1;
            } else {
                const float sc = (c < C_EMBED) ? 0.125f : 1.0f;   // Q-scale fold
                uint32_t* Co = (uint32_t*)Cm;
                uint2 v0, v1;
                v0.x = f2tf32((acc[mt][nt][0] + b0) * sc);
                v0.y = f2tf32((acc[mt][nt][1] + b1) * sc);
                v1.x = f2tf32((acc[mt][nt][2] + b0) * sc);
                v1.y = f2tf32((acc[mt][nt][3] + b1) * sc);
                *(uint2*)&Co[(size_t)r * N + c] = v0;
                *(uint2*)&Co[(size_t)(r + 8) * N + c] = v1;
            }
        }
    }
}

// ===========================================================================
// tf32-bit mma flash attention (causal), 128-row Q tiles, cp.async K/V,
// single barrier per key tile, largest-qt-first, K/P fragments via ldmatrix.
// ===========================================================================
#define A_KW 68
#define A_VW 72
#define A_KBUF (64 * A_KW)
#define A_VBUF (64 * A_VW)
#define A_VOFF (2 * A_KBUF)
#define A_POFF (A_VOFF + 2 * A_VBUF)
#define ATTN_SMEM_BYTES ((A_POFF + 128 * 68) * 4)   // 106496

__global__ void __launch_bounds__(256) attn_tc_kernel(
    const uint32_t* __restrict__ qkv, uint32_t* __restrict__ attout)
{
    extern __shared__ uint32_t asm_[];
    const uint32_t sb = smem_u32(asm_);
    uint32_t* Ps = asm_ + A_POFF;
    const uint32_t sbP = sb + (uint32_t)(A_POFF * 4);

    const int qt  = (int)gridDim.x - 1 - (int)blockIdx.x;   // largest-first
    const int h   = blockIdx.y;
    const int b   = blockIdx.z;
    const int tid = threadIdx.x;
    const int w   = tid >> 5;
    const int L   = tid & 31;
    const int gid = L >> 2;
    const int tig = L & 3;
    const int wrow = w * 16;

    // ldmatrix lane maps
    // K: mat0 rows+0 k+0 | mat1 rows+0 k+4 | mat2 rows+8 k+0 | mat3 rows+8 k+4
    const int km = L >> 3;
    const int krow_off = ((km >> 1) << 3) + (L & 7);
    const int kcol_off = (km & 1) << 2;
    // P: mat0 rows+0 k+0 | mat1 rows+8 k+0 | mat2 rows+0 k+4 | mat3 rows+8 k+4
    const int pm = L >> 3;
    const int prow_off = ((pm & 1) << 3) + (L & 7);
    const int pcol_off = (pm >> 1) << 2;

    const uint32_t* qbase = qkv + (size_t)b * SEQ * C3 + h * HD;
    const uint32_t* kbase = qbase + C_EMBED;
    const uint32_t* vbase = qbase + 2 * C_EMBED;

    // ---- Q fragments: ready tf32 bits straight from gmem ----
    uint32_t qf[8][4];
    {
        const uint32_t* qr0 = qbase + (size_t)(qt * 128 + wrow + gid) * C3;
        const uint32_t* qr1 = qr0 + 8 * C3;
#pragma unroll
        for (int ks = 0; ks < 8; ks++) {
            const int c = 8 * ks + tig;
            qf[ks][0] = qr0[c];
            qf[ks][1] = qr1[c];
            qf[ks][2] = qr0[c + 4];
            qf[ks][3] = qr1[c + 4];
        }
    }

    float o[8][4];
#pragma unroll
    for (int nt = 0; nt < 8; nt++)
#pragma unroll
        for (int e = 0; e < 4; e++) o[nt][e] = 0.f;
    float m0 = -1e30f, m1 = -1e30f, l0 = 0.f, l1 = 0.f;

    const int rmax_w = qt * 128 + wrow + 15;
    const int ntiles = 2 * qt + 2;

    auto issue = [&](int j, int bf) {
#pragma unroll
        for (int u = 0; u < 4; u++) {
            int fid = u * 256 + tid;
            int r   = fid >> 4;
            int c4  = fid & 15;
            const size_t grow = (size_t)(j * 64 + r) * C3 + c4 * 4;
            cp_async16(sb + (uint32_t)((bf * A_KBUF + r * A_KW + c4 * 4) * 4),
                       kbase + grow);
            cp_async16(sb + (uint32_t)((A_VOFF + bf * A_VBUF + r * A_VW + c4 * 4) * 4),
                       vbase + grow);
        }
    };

    issue(0, 0);
    cp_commit();

    for (int j0 = 0; j0 < ntiles; j0++) {
        cp_wait0();
        __syncthreads();
        if (j0 + 1 < ntiles) { issue(j0 + 1, (j0 + 1) & 1); cp_commit(); }

        if (j0 * 64 <= rmax_w) {
            const int bf = j0 & 1;
            const uint32_t sbK = sb + (uint32_t)(bf * A_KBUF * 4);
            const uint32_t* Vf = asm_ + A_VOFF + bf * A_VBUF;

            // ---- S = Q K^T (K fragments via ldmatrix.x4) ----
            float s[8][4];
#pragma unroll
            for (int nt = 0; nt < 8; nt++)
#pragma unroll
                for (int e = 0; e < 4; e++) s[nt][e] = 0.f;

#pragma unroll
            for (int ks = 0; ks < 8; ks++) {
#pragma unroll
                for (int ntp = 0; ntp < 4; ntp++) {
                    uint32_t kb4[4];
                    ldmx4(kb4, sbK + (uint32_t)(((ntp * 16 + krow_off) * A_KW
                                                 + 8 * ks + kcol_off) * 4));
                    mma16n8k8(s[2 * ntp],     qf[ks], kb4);
                    mma16n8k8(s[2 * ntp + 1], qf[ks], kb4 + 2);
                }
            }

            // ---- causal mask ----
            const int qr0 = qt * 128 + wrow + gid;
            if (j0 * 64 + 63 > qt * 128 + wrow) {
#pragma unroll
                for (int nt = 0; nt < 8; nt++) {
                    const int c0g = j0 * 64 + nt * 8 + 2 * tig;
                    if (c0g     > qr0)     s[nt][0] = -1e30f;
                    if (c0g + 1 > qr0)     s[nt][1] = -1e30f;
                    if (c0g     > qr0 + 8) s[nt][2] = -1e30f;
                    if (c0g + 1 > qr0 + 8) s[nt][3] = -1e30f;
                }
            }

            // ---- online softmax ----
            float mloc0 = -1e30f, mloc1 = -1e30f;
#pragma unroll
            for (int nt = 0; nt < 8; nt++) {
                mloc0 = fmaxf(mloc0, fmaxf(s[nt][0], s[nt][1]));
                mloc1 = fmaxf(mloc1, fmaxf(s[nt][2], s[nt][3]));
            }
            mloc0 = fmaxf(mloc0, __shfl_xor_sync(0xffffffffu, mloc0, 1));
            mloc0 = fmaxf(mloc0, __shfl_xor_sync(0xffffffffu, mloc0, 2));
            mloc1 = fmaxf(mloc1, __shfl_xor_sync(0xffffffffu, mloc1, 1));
            mloc1 = fmaxf(mloc1, __shfl_xor_sync(0xffffffffu, mloc1, 2));

            const float mn0 = fmaxf(m0, mloc0);
            const float mn1 = fmaxf(m1, mloc1);
            const float cr0 = __expf(m0 - mn0);
            const float cr1 = __expf(m1 - mn1);

            float rs0 = 0.f, rs1 = 0.f;
#pragma unroll
            for (int nt = 0; nt < 8; nt++) {
                s[nt][0] = __expf(s[nt][0] - mn0);
                s[nt][1] = __expf(s[nt][1] - mn0);
                s[nt][2] = __expf(s[nt][2] - mn1);
                s[nt][3] = __expf(s[nt][3] - mn1);
                rs0 += s[nt][0] + s[nt][1];
                rs1 += s[nt][2] + s[nt][3];
            }
            rs0 += __shfl_xor_sync(0xffffffffu, rs0, 1);
            rs0 += __shfl_xor_sync(0xffffffffu, rs0, 2);
            rs1 += __shfl_xor_sync(0xffffffffu, rs1, 1);
            rs1 += __shfl_xor_sync(0xffffffffu, rs1, 2);

            l0 = l0 * cr0 + rs0;
            l1 = l1 * cr1 + rs1;
            m0 = mn0;
            m1 = mn1;
#pragma unroll
            for (int nt = 0; nt < 8; nt++) {
                o[nt][0] *= cr0; o[nt][1] *= cr0;
                o[nt][2] *= cr1; o[nt][3] *= cr1;
            }

            // ---- stage P (warp-private rows) ----
#pragma unroll
            for (int nt = 0; nt < 8; nt++) {
                const int pb = (wrow + gid) * 68 + nt * 8 + 2 * tig;
                Ps[pb]              = f2tf32(s[nt][0]);
                Ps[pb + 1]          = f2tf32(s[nt][1]);
                Ps[pb + 8 * 68]     = f2tf32(s[nt][2]);
                Ps[pb + 8 * 68 + 1] = f2tf32(s[nt][3]);
            }
            __syncwarp();

            // ---- O += P V (P fragments via ldmatrix.x4) ----
#pragma unroll
            for (int ks = 0; ks < 8; ks++) {
                uint32_t pa[4];
                ldmx4(pa, sbP + (uint32_t)(((wrow + prow_off) * 68
                                            + 8 * ks + pcol_off) * 4));
#pragma unroll
                for (int nt = 0; nt < 8; nt++) {
                    uint32_t vb[2];
                    const int rv = (8 * ks + tig) * A_VW + nt * 8 + gid;
                    vb[0] = Vf[rv];
                    vb[1] = Vf[rv + 4 * A_VW];
                    mma16n8k8(o[nt], pa, vb);
                }
            }
            __syncwarp();
        }
    }

    // ---- normalize + write tf32 bits ----
    const float inv0 = 1.f / l0;
    const float inv1 = 1.f / l1;
    const int t0 = qt * 128 + wrow + gid;
#pragma unroll
    for (int nt = 0; nt < 8; nt++) {
        const int d = h * HD + nt * 8 + 2 * tig;
        uint2 v0, v1;
        v0.x = f2tf32(o[nt][0] * inv0);
        v0.y = f2tf32(o[nt][1] * inv0);
        v1.x = f2tf32(o[nt][2] * inv1);
        v1.y = f2tf32(o[nt][3] * inv1);
        *(uint2*)&attout[(size_t)(b * SEQ + t0) * C_EMBED + d] = v0;
        *(uint2*)&attout[(size_t)(b * SEQ + t0 + 8) * C_EMBED + d] = v1;
    }
}

// ---------------------------------------------------------------------------
extern "C" void kernel_launch(void* const* d_in, const int* in_sizes, int n_in,
                              void* d_out, int out_size)
{
    const float* x     = (const float*)d_in[0];
    const float* Wqkv  = (const float*)d_in[1];
    const float* bqkv  = (const float*)d_in[2];
    const float* Wproj = (const float*)d_in[3];
    const float* bproj = (const float*)d_in[4];
    float* out = (float*)d_out;

    uint32_t *qkv, *att, *xt, *wqkvt, *wprojt;
    cudaGetSymbolAddress((void**)&qkv, g_qkv);
    cudaGetSymbolAddress((void**)&att, g_att);
    cudaGetSymbolAddress((void**)&xt, g_xt);
    cudaGetSymbolAddress((void**)&wqkvt, g_wqkvt);
    cudaGetSymbolAddress((void**)&wprojt, g_wprojt);

    cudaFuncSetAttribute(gemm_tf32_kernel<0>, cudaFuncAttributeMaxDynamicSharedMemorySize,
                         GEMM_SMEM_BYTES);
    cudaFuncSetAttribute(gemm_tf32_kernel<1>, cudaFuncAttributeMaxDynamicSharedMemorySize,
                         GEMM_SMEM_BYTES);
    cudaFuncSetAttribute(attn_tc_kernel, cudaFuncAttributeMaxDynamicSharedMemorySize,
                         ATTN_SMEM_BYTES);

    // 0) pre-round inputs/weights to tf32 bits
    {
        int n4x = (MROWS * C_EMBED) / 4;
        cvt_tf32_kernel<<<(n4x + 255) / 256, 256>>>((const float4*)x, (uint4*)xt, n4x);
        int n4w = (C_EMBED * C3) / 4;
        cvt_tf32_kernel<<<(n4w + 255) / 256, 256>>>((const float4*)Wqkv, (uint4*)wqkvt, n4w);
        int n4p = (C_EMBED * C_EMBED) / 4;
        cvt_tf32_kernel<<<(n4p + 255) / 256, 256>>>((const float4*)Wproj, (uint4*)wprojt, n4p);
    }

    // 1) QKV projection -> tf32 bits, Q-scale folded
    dim3 g1(C3 / 128, MROWS / 128);
    gemm_tf32_kernel<1><<<g1, 256, GEMM_SMEM_BYTES>>>(xt, wqkvt, bqkv, (float*)qkv,
                                                      MROWS, C3, C_EMBED);

    // 2) Causal flash attention -> tf32 bits
    dim3 g2(SEQ / 128, NH, BATCH);
    attn_tc_kernel<<<g2, 256, ATTN_SMEM_BYTES>>>(qkv, att);

    // 3) Output projection -> fp32
    dim3 g3(C_EMBED / 128, MROWS / 128);
    gemm_tf32_kernel<0><<<g3, 256, GEMM_SMEM_BYTES>>>(att, wprojt, bproj, out,
                                                      MROWS, C_EMBED, C_EMBED);
}